// round 1
// baseline (speedup 1.0000x reference)
#include <cuda_runtime.h>
#include <math.h>

#define D_    512
#define HID_  2048
#define L_    4
#define V_    32000
#define B_    2
#define T_    1025
#define S_    128
#define NH_   8
#define DH_   64
#define NT_   256          // B_*S_ tokens per chunk
#define NCH_  8
#define LR_   0.0003f
#define ASC_  0.125f       // 1/sqrt(DH)

#define ND_  (NT_*D_)      // 131072
#define NH1_ (NT_*HID_)    // 524288
#define NQ_  (NT_*3*D_)    // 393216
#define NA_  (B_*NH_*S_*S_)// 262144

// ---------------- device scratch (static; no allocation allowed) ----------------
__device__ float g_W1[L_*D_*HID_];
__device__ float g_W2[L_*HID_*D_];
__device__ float g_b1[L_*HID_];
__device__ float g_b2[L_*D_];
__device__ float g_h[L_*ND_];      // h_in per layer
__device__ float g_hmid[L_*ND_];   // h after attention residual
__device__ float g_hfin[ND_];
__device__ float g_m[L_*ND_];      // LN2 output
__device__ float g_qkv[L_*NQ_];
__device__ float g_att[L_*NA_];
__device__ float g_z1[L_*NH1_];
__device__ float g_gl[L_*NH1_];    // gelu(z1)
__device__ float g_abuf[ND_];
__device__ float g_obuf[ND_];
__device__ float g_dh[ND_];
__device__ float g_dtH[NH1_];
__device__ float g_dtD[ND_];
__device__ float g_dob[ND_];
__device__ float g_dqkv[NQ_];
__device__ float g_ds[NA_];
__device__ float g_dlog[NT_*V_];
__device__ float g_rmax[NT_];
__device__ float g_rsum[NT_];

// ---------------- generic fp32 GEMM: C = alpha*op(A)op(B) + beta*C + bias ----------------
// row-major. !TA: A[m*lda+k]; TA: A[k*lda+m]. !TB: B[k*ldb+n]; TB: B[n*ldb+k].
template<int TA, int TB>
__global__ void __launch_bounds__(256) gemm_k(
    int M, int N, int K, float alpha,
    const float* __restrict__ A, int lda,
    const float* __restrict__ B, int ldb,
    float beta, float* __restrict__ C, int ldc,
    const float* __restrict__ bias)
{
    __shared__ __align__(16) float As[16*68];
    __shared__ __align__(16) float Bs[16*68];
    const int tid = threadIdx.x;
    const int m0 = blockIdx.y * 64, n0 = blockIdx.x * 64;
    const int tx = tid & 15, ty = tid >> 4;
    float acc[4][4] = {};

    for (int k0 = 0; k0 < K; k0 += 16) {
        if (!TA) {
            int r = tid >> 2, c4 = (tid & 3) * 4;
            float4 a4 = *(const float4*)(A + (size_t)(m0 + r) * lda + k0 + c4);
            As[(c4+0)*68 + r] = a4.x; As[(c4+1)*68 + r] = a4.y;
            As[(c4+2)*68 + r] = a4.z; As[(c4+3)*68 + r] = a4.w;
        } else {
            int r = tid >> 4, c4 = (tid & 15) * 4;
            float4 a4 = *(const float4*)(A + (size_t)(k0 + r) * lda + m0 + c4);
            *(float4*)(&As[r*68 + c4]) = a4;
        }
        if (!TB) {
            int r = tid >> 4, c4 = (tid & 15) * 4;
            float4 b4 = *(const float4*)(B + (size_t)(k0 + r) * ldb + n0 + c4);
            *(float4*)(&Bs[r*68 + c4]) = b4;
        } else {
            int r = tid >> 2, c4 = (tid & 3) * 4;
            float4 b4 = *(const float4*)(B + (size_t)(n0 + r) * ldb + k0 + c4);
            Bs[(c4+0)*68 + r] = b4.x; Bs[(c4+1)*68 + r] = b4.y;
            Bs[(c4+2)*68 + r] = b4.z; Bs[(c4+3)*68 + r] = b4.w;
        }
        __syncthreads();
        #pragma unroll
        for (int k = 0; k < 16; k++) {
            float4 a4 = *(const float4*)(&As[k*68 + ty*4]);
            float4 b4 = *(const float4*)(&Bs[k*68 + tx*4]);
            float a[4] = {a4.x, a4.y, a4.z, a4.w};
            float b[4] = {b4.x, b4.y, b4.z, b4.w};
            #pragma unroll
            for (int i = 0; i < 4; i++)
                #pragma unroll
                for (int j = 0; j < 4; j++)
                    acc[i][j] += a[i] * b[j];
        }
        __syncthreads();
    }

    const int m = m0 + ty * 4, n = n0 + tx * 4;
    #pragma unroll
    for (int i = 0; i < 4; i++) {
        size_t cb = (size_t)(m + i) * ldc + n;
        #pragma unroll
        for (int j = 0; j < 4; j++) {
            float v = alpha * acc[i][j];
            if (beta != 0.f) v += beta * C[cb + j];
            if (bias) v += bias[n + j];
            C[cb + j] = v;
        }
    }
}

static inline void gemm(int TA, int TB, int M, int N, int K, float alpha,
                        const float* A, int lda, const float* B, int ldb,
                        float beta, float* C, int ldc, const float* bias)
{
    dim3 g(N / 64, M / 64);
    if (!TA && !TB)      gemm_k<0,0><<<g,256>>>(M,N,K,alpha,A,lda,B,ldb,beta,C,ldc,bias);
    else if (!TA && TB)  gemm_k<0,1><<<g,256>>>(M,N,K,alpha,A,lda,B,ldb,beta,C,ldc,bias);
    else if (TA && !TB)  gemm_k<1,0><<<g,256>>>(M,N,K,alpha,A,lda,B,ldb,beta,C,ldc,bias);
    else                 gemm_k<1,1><<<g,256>>>(M,N,K,alpha,A,lda,B,ldb,beta,C,ldc,bias);
}

// ---------------- misc kernels ----------------
__global__ void __launch_bounds__(256) copy_k(const float* __restrict__ a, float* __restrict__ b) {
    int i = blockIdx.x * 256 + threadIdx.x;
    b[i] = a[i];
}

__global__ void __launch_bounds__(256) embed_k(const int* __restrict__ x,
    const float* __restrict__ emb, const float* __restrict__ pos,
    float* __restrict__ h, int off)
{
    int idx = blockIdx.x * 256 + threadIdx.x;     // NT_*D_
    int row = idx >> 9, d = idx & 511;
    int b = row >> 7, s = row & 127;
    int tok = x[b * T_ + off + s];
    h[idx] = emb[(size_t)tok * D_ + d] + pos[s * D_ + d];
}

// LayerNorm forward: one block (256 thr) per row of D_=512
__global__ void __launch_bounds__(256) ln_fwd(const float* __restrict__ x,
    const float* __restrict__ s, const float* __restrict__ b, float* __restrict__ y)
{
    __shared__ float red[256];
    int row = blockIdx.x, tid = threadIdx.x;
    const float* xr = x + (size_t)row * D_;
    float x0 = xr[tid], x1 = xr[tid + 256];
    red[tid] = x0 + x1; __syncthreads();
    for (int w = 128; w > 0; w >>= 1) { if (tid < w) red[tid] += red[tid + w]; __syncthreads(); }
    float mean = red[0] * (1.f / D_); __syncthreads();
    float d0 = x0 - mean, d1 = x1 - mean;
    red[tid] = d0 * d0 + d1 * d1; __syncthreads();
    for (int w = 128; w > 0; w >>= 1) { if (tid < w) red[tid] += red[tid + w]; __syncthreads(); }
    float rstd = rsqrtf(red[0] * (1.f / D_) + 1e-5f);
    float* yr = y + (size_t)row * D_;
    yr[tid]       = d0 * rstd * s[tid]       + b[tid];
    yr[tid + 256] = d1 * rstd * s[tid + 256] + b[tid + 256];
}

// LayerNorm backward: dx = rstd*(s*dy - mean(s*dy) - xhat*mean(s*dy*xhat)); write or accumulate
__global__ void __launch_bounds__(256) ln_bwd(const float* __restrict__ x,
    const float* __restrict__ dy, const float* __restrict__ s,
    float* __restrict__ dacc, int accum)
{
    __shared__ float red[256];
    int row = blockIdx.x, tid = threadIdx.x;
    const float* xr = x + (size_t)row * D_;
    const float* dr = dy + (size_t)row * D_;
    float x0 = xr[tid], x1 = xr[tid + 256];
    red[tid] = x0 + x1; __syncthreads();
    for (int w = 128; w > 0; w >>= 1) { if (tid < w) red[tid] += red[tid + w]; __syncthreads(); }
    float mean = red[0] * (1.f / D_); __syncthreads();
    float d0 = x0 - mean, d1 = x1 - mean;
    red[tid] = d0 * d0 + d1 * d1; __syncthreads();
    for (int w = 128; w > 0; w >>= 1) { if (tid < w) red[tid] += red[tid + w]; __syncthreads(); }
    float rstd = rsqrtf(red[0] * (1.f / D_) + 1e-5f); __syncthreads();
    float xh0 = d0 * rstd, xh1 = d1 * rstd;
    float g0 = s[tid] * dr[tid], g1 = s[tid + 256] * dr[tid + 256];
    red[tid] = g0 + g1; __syncthreads();
    for (int w = 128; w > 0; w >>= 1) { if (tid < w) red[tid] += red[tid + w]; __syncthreads(); }
    float t1 = red[0] * (1.f / D_); __syncthreads();
    red[tid] = g0 * xh0 + g1 * xh1; __syncthreads();
    for (int w = 128; w > 0; w >>= 1) { if (tid < w) red[tid] += red[tid + w]; __syncthreads(); }
    float t2 = red[0] * (1.f / D_);
    float dx0 = rstd * (g0 - t1 - xh0 * t2);
    float dx1 = rstd * (g1 - t1 - xh1 * t2);
    float* ar = dacc + (size_t)row * D_;
    if (accum) { ar[tid] += dx0; ar[tid + 256] += dx1; }
    else       { ar[tid]  = dx0; ar[tid + 256]  = dx1; }
}

__global__ void __launch_bounds__(256) gelu_fwd(const float* __restrict__ z, float* __restrict__ g) {
    int i = blockIdx.x * 256 + threadIdx.x;
    float xv = z[i];
    float u = 0.7978845608028654f * (xv + 0.044715f * xv * xv * xv);
    g[i] = 0.5f * xv * (1.f + tanhf(u));
}

__global__ void __launch_bounds__(256) gelu_bwd(float* __restrict__ dg, const float* __restrict__ z) {
    int i = blockIdx.x * 256 + threadIdx.x;
    float xv = z[i], x2 = xv * xv;
    float u = 0.7978845608028654f * (xv + 0.044715f * xv * x2);
    float t = tanhf(u);
    float der = 0.5f * (1.f + t)
              + 0.5f * xv * (1.f - t * t) * 0.7978845608028654f * (1.f + 3.f * 0.044715f * x2);
    dg[i] *= der;
}

// attention forward: one block per (query row, head, batch); stores att row + o
__global__ void __launch_bounds__(128) attn_fwd(const float* __restrict__ qkv,
    float* __restrict__ att, float* __restrict__ obuf)
{
    int qi = blockIdx.x, h = blockIdx.y, b = blockIdx.z, tid = threadIdx.x;
    __shared__ float qs[DH_]; __shared__ float sc[S_]; __shared__ float red[128];
    int row = b * S_ + qi;
    if (tid < DH_) qs[tid] = qkv[(size_t)row * (3*D_) + h * DH_ + tid];
    __syncthreads();
    float sj = -1e30f;
    if (tid <= qi) {
        const float* kp = qkv + (size_t)(b * S_ + tid) * (3*D_) + D_ + h * DH_;
        float a = 0.f;
        #pragma unroll
        for (int d = 0; d < DH_; d++) a += qs[d] * kp[d];
        sj = a * ASC_;
    }
    red[tid] = sj; __syncthreads();
    for (int w = 64; w > 0; w >>= 1) { if (tid < w) red[tid] = fmaxf(red[tid], red[tid + w]); __syncthreads(); }
    float mx = red[0]; __syncthreads();
    float e = (tid <= qi) ? expf(sj - mx) : 0.f;
    red[tid] = e; __syncthreads();
    for (int w = 64; w > 0; w >>= 1) { if (tid < w) red[tid] += red[tid + w]; __syncthreads(); }
    float a = e / red[0];
    size_t arow = ((size_t)(b * NH_ + h) * S_ + qi) * S_;
    att[arow + tid] = a;
    sc[tid] = a; __syncthreads();
    if (tid < DH_) {
        float acc = 0.f;
        for (int j = 0; j <= qi; j++)
            acc += sc[j] * qkv[(size_t)(b * S_ + j) * (3*D_) + 2*D_ + h * DH_ + tid];
        obuf[(size_t)row * D_ + h * DH_ + tid] = acc;
    }
}

// attention backward pass 1: ds row + dq row
__global__ void __launch_bounds__(128) attn_bwd1(const float* __restrict__ qkv,
    const float* __restrict__ att, const float* __restrict__ dob,
    float* __restrict__ dsbuf, float* __restrict__ dqkv)
{
    int qi = blockIdx.x, h = blockIdx.y, b = blockIdx.z, tid = threadIdx.x;
    __shared__ float dov[DH_]; __shared__ float sc[S_]; __shared__ float red[128];
    int row = b * S_ + qi;
    if (tid < DH_) dov[tid] = dob[(size_t)row * D_ + h * DH_ + tid];
    __syncthreads();
    size_t arow = ((size_t)(b * NH_ + h) * S_ + qi) * S_;
    float a = att[arow + tid];
    float datt = 0.f;
    if (tid <= qi) {
        const float* vp = qkv + (size_t)(b * S_ + tid) * (3*D_) + 2*D_ + h * DH_;
        #pragma unroll
        for (int d = 0; d < DH_; d++) datt += dov[d] * vp[d];
    }
    red[tid] = a * datt; __syncthreads();
    for (int w = 64; w > 0; w >>= 1) { if (tid < w) red[tid] += red[tid + w]; __syncthreads(); }
    float tot = red[0];
    float ds = a * (datt - tot);
    dsbuf[arow + tid] = ds;
    sc[tid] = ds; __syncthreads();
    if (tid < DH_) {
        float acc = 0.f;
        for (int j = 0; j <= qi; j++)
            acc += sc[j] * qkv[(size_t)(b * S_ + j) * (3*D_) + D_ + h * DH_ + tid];
        dqkv[(size_t)row * (3*D_) + h * DH_ + tid] = acc * ASC_;
    }
}

// attention backward pass 2: dk, dv rows (transposed accumulation)
__global__ void __launch_bounds__(64) attn_bwd2(const float* __restrict__ qkv,
    const float* __restrict__ att, const float* __restrict__ dob,
    const float* __restrict__ dsbuf, float* __restrict__ dqkv)
{
    int j = blockIdx.x, h = blockIdx.y, b = blockIdx.z, d = threadIdx.x;
    size_t bh = (size_t)(b * NH_ + h) * S_;
    float dk = 0.f, dv = 0.f;
    for (int q = j; q < S_; q++) {
        float ds = dsbuf[(bh + q) * S_ + j];
        float a  = att[(bh + q) * S_ + j];
        dk += ds * qkv[(size_t)(b * S_ + q) * (3*D_) + h * DH_ + d];
        dv += a  * dob[(size_t)(b * S_ + q) * D_ + h * DH_ + d];
    }
    dqkv[(size_t)(b * S_ + j) * (3*D_) + D_   + h * DH_ + d] = dk * ASC_;
    dqkv[(size_t)(b * S_ + j) * (3*D_) + 2*D_ + h * DH_ + d] = dv;
}

// bias SGD: b[c] -= LR * colsum(dY)
__global__ void __launch_bounds__(256) bias_sgd(const float* __restrict__ dY,
    float* __restrict__ bv, int C)
{
    int c = blockIdx.x * 256 + threadIdx.x;
    float s = 0.f;
    for (int i = 0; i < NT_; i++) s += dY[(size_t)i * C + c];
    bv[c] -= LR_ * s;
}

// per-row softmax stats over V_ (reads logits from d_out)
__global__ void __launch_bounds__(256) smax_stats(const float* __restrict__ out, int off,
    float* __restrict__ rmax, float* __restrict__ rsum)
{
    __shared__ float red[256];
    int i = blockIdx.x, tid = threadIdx.x;
    int b = i >> 7, s = i & 127;
    const float* lp = out + ((size_t)(b * (NCH_*S_) + off + s)) * V_;
    float m = -1e30f;
    for (int v = tid; v < V_; v += 256) m = fmaxf(m, lp[v]);
    red[tid] = m; __syncthreads();
    for (int w = 128; w > 0; w >>= 1) { if (tid < w) red[tid] = fmaxf(red[tid], red[tid + w]); __syncthreads(); }
    m = red[0]; __syncthreads();
    float sum = 0.f;
    for (int v = tid; v < V_; v += 256) sum += expf(lp[v] - m);
    red[tid] = sum; __syncthreads();
    for (int w = 128; w > 0; w >>= 1) { if (tid < w) red[tid] += red[tid + w]; __syncthreads(); }
    if (tid == 0) { rmax[i] = m; rsum[i] = red[0]; }
}

// dlogits = (softmax - onehot(tgt)) / NT_
__global__ void __launch_bounds__(256) dlogits_k(const float* __restrict__ out,
    const int* __restrict__ x, int off, const float* __restrict__ rmax,
    const float* __restrict__ rsum, float* __restrict__ dl)
{
    int v = blockIdx.x * 256 + threadIdx.x;
    int i = blockIdx.y;
    int b = i >> 7, s = i & 127;
    float l = out[((size_t)(b * (NCH_*S_) + off + s)) * V_ + v];
    float p = expf(l - rmax[i]) / rsum[i];
    int tgt = x[b * T_ + off + s + 1];
    dl[(size_t)i * V_ + v] = (p - (v == tgt ? 1.f : 0.f)) * (1.f / NT_);
}

// ---------------- host ----------------
static float* P(const void* sym) { void* p = 0; cudaGetSymbolAddress(&p, sym); return (float*)p; }

extern "C" void kernel_launch(void* const* d_in, const int* in_sizes, int n_in,
                              void* d_out, int out_size)
{
    const int*   x     = (const int*)  d_in[0];
    const float* emb   = (const float*)d_in[1];
    const float* pos   = (const float*)d_in[2];
    const float* ln1s  = (const float*)d_in[3];
    const float* ln1b  = (const float*)d_in[4];
    const float* Wqkv  = (const float*)d_in[5];
    const float* bqkv  = (const float*)d_in[6];
    const float* Wo    = (const float*)d_in[7];
    const float* bo    = (const float*)d_in[8];
    const float* ln2s  = (const float*)d_in[9];
    const float* ln2b  = (const float*)d_in[10];
    const float* W1i   = (const float*)d_in[11];
    const float* b1i   = (const float*)d_in[12];
    const float* W2i   = (const float*)d_in[13];
    const float* b2i   = (const float*)d_in[14];
    const float* lnfs  = (const float*)d_in[15];
    const float* lnfb  = (const float*)d_in[16];
    const float* Whead = (const float*)d_in[17];
    const float* bhead = (const float*)d_in[18];
    float* out = (float*)d_out;

    float *pW1 = P(g_W1), *pW2 = P(g_W2), *pb1 = P(g_b1), *pb2 = P(g_b2);
    float *ph = P(g_h), *phmid = P(g_hmid), *phfin = P(g_hfin), *pm = P(g_m);
    float *pqkv = P(g_qkv), *patt = P(g_att), *pz1 = P(g_z1), *pgl = P(g_gl);
    float *pabuf = P(g_abuf), *pobuf = P(g_obuf), *pdh = P(g_dh);
    float *pdtH = P(g_dtH), *pdtD = P(g_dtD), *pdob = P(g_dob);
    float *pdqkv = P(g_dqkv), *pds = P(g_ds), *pdlog = P(g_dlog);
    float *prmax = P(g_rmax), *prsum = P(g_rsum);

    // working copies of trainable MLP params
    copy_k<<<(L_*D_*HID_)/256, 256>>>(W1i, pW1);
    copy_k<<<(L_*HID_*D_)/256, 256>>>(W2i, pW2);
    copy_k<<<(L_*HID_)/256, 256>>>(b1i, pb1);
    copy_k<<<(L_*D_)/256, 256>>>(b2i, pb2);

    for (int c = 0; c < NCH_; c++) {
        const int off = c * S_;

        // ---------------- forward ----------------
        embed_k<<<ND_/256, 256>>>(x, emb, pos, ph, off);
        for (int l = 0; l < L_; l++) {
            float* hin = ph + (size_t)l * ND_;
            ln_fwd<<<NT_, 256>>>(hin, ln1s + l*D_, ln1b + l*D_, pabuf);
            gemm(0,0, NT_, 3*D_, D_, 1.f, pabuf, D_, Wqkv + (size_t)l*D_*3*D_, 3*D_,
                 0.f, pqkv + (size_t)l*NQ_, 3*D_, bqkv + l*3*D_);
            attn_fwd<<<dim3(S_,NH_,B_), 128>>>(pqkv + (size_t)l*NQ_, patt + (size_t)l*NA_, pobuf);
            copy_k<<<ND_/256, 256>>>(hin, phmid + (size_t)l*ND_);
            gemm(0,0, NT_, D_, D_, 1.f, pobuf, D_, Wo + (size_t)l*D_*D_, D_,
                 1.f, phmid + (size_t)l*ND_, D_, bo + l*D_);
            ln_fwd<<<NT_, 256>>>(phmid + (size_t)l*ND_, ln2s + l*D_, ln2b + l*D_, pm + (size_t)l*ND_);
            gemm(0,0, NT_, HID_, D_, 1.f, pm + (size_t)l*ND_, D_, pW1 + (size_t)l*D_*HID_, HID_,
                 0.f, pz1 + (size_t)l*NH1_, HID_, pb1 + l*HID_);
            gelu_fwd<<<NH1_/256, 256>>>(pz1 + (size_t)l*NH1_, pgl + (size_t)l*NH1_);
            float* hout = (l < L_-1) ? ph + (size_t)(l+1)*ND_ : phfin;
            copy_k<<<ND_/256, 256>>>(phmid + (size_t)l*ND_, hout);
            gemm(0,0, NT_, D_, HID_, 1.f, pgl + (size_t)l*NH1_, HID_, pW2 + (size_t)l*HID_*D_, D_,
                 1.f, hout, D_, pb2 + l*D_);
        }
        ln_fwd<<<NT_, 256>>>(phfin, lnfs, lnfb, pabuf);
        for (int b = 0; b < B_; b++)
            gemm(0,0, S_, V_, D_, 1.f, pabuf + (size_t)b*S_*D_, D_, Whead, V_,
                 0.f, out + ((size_t)(b*(NCH_*S_) + off)) * V_, V_, bhead);

        // ---------------- backward ----------------
        smax_stats<<<NT_, 256>>>(out, off, prmax, prsum);
        dlogits_k<<<dim3(V_/256, NT_), 256>>>(out, x, off, prmax, prsum, pdlog);
        gemm(0,1, NT_, D_, V_, 1.f, pdlog, V_, Whead, V_, 0.f, pdtD, D_, 0);
        ln_bwd<<<NT_, 256>>>(phfin, pdtD, lnfs, pdh, 0);

        for (int l = L_-1; l >= 0; l--) {
            // MLP backward + fused SGD update
            gemm(0,1, NT_, HID_, D_, 1.f, pdh, D_, pW2 + (size_t)l*HID_*D_, D_, 0.f, pdtH, HID_, 0);
            gemm(1,0, HID_, D_, NT_, -LR_, pgl + (size_t)l*NH1_, HID_, pdh, D_,
                 1.f, pW2 + (size_t)l*HID_*D_, D_, 0);
            bias_sgd<<<D_/256, 256>>>(pdh, pb2 + l*D_, D_);
            gelu_bwd<<<NH1_/256, 256>>>(pdtH, pz1 + (size_t)l*NH1_);
            gemm(0,1, NT_, D_, HID_, 1.f, pdtH, HID_, pW1 + (size_t)l*D_*HID_, HID_, 0.f, pdtD, D_, 0);
            gemm(1,0, D_, HID_, NT_, -LR_, pm + (size_t)l*ND_, D_, pdtH, HID_,
                 1.f, pW1 + (size_t)l*D_*HID_, HID_, 0);
            bias_sgd<<<HID_/256, 256>>>(pdtH, pb1 + l*HID_, HID_);
            ln_bwd<<<NT_, 256>>>(phmid + (size_t)l*ND_, pdtD, ln2s + l*D_, pdh, 1);

            // attention backward (no weight grads needed)
            gemm(0,1, NT_, D_, D_, 1.f, pdh, D_, Wo + (size_t)l*D_*D_, D_, 0.f, pdob, D_, 0);
            attn_bwd1<<<dim3(S_,NH_,B_), 128>>>(pqkv + (size_t)l*NQ_, patt + (size_t)l*NA_, pdob, pds, pdqkv);
            attn_bwd2<<<dim3(S_,NH_,B_), 64>>>(pqkv + (size_t)l*NQ_, patt + (size_t)l*NA_, pdob, pds, pdqkv);
            gemm(0,1, NT_, D_, 3*D_, 1.f, pdqkv, 3*D_, Wqkv + (size_t)l*D_*3*D_, 3*D_, 0.f, pdtD, D_, 0);
            ln_bwd<<<NT_, 256>>>(ph + (size_t)l*ND_, pdtD, ln1s + l*D_, pdh, 1);
        }
    }
    (void)in_sizes; (void)n_in; (void)out_size;
}

// round 3
// speedup vs baseline: 1.2379x; 1.2379x over previous
#include <cuda_runtime.h>
#include <math.h>

#define D_    512
#define HID_  2048
#define L_    4
#define V_    32000
#define B_    2
#define T_    1025
#define S_    128
#define NH_   8
#define DH_   64
#define NT_   256
#define NCH_  8
#define LR_   0.0003f
#define ASC_  0.125f

#define ND_  (NT_*D_)
#define NH1_ (NT_*HID_)
#define NQ_  (NT_*3*D_)
#define NA_  (B_*NH_*S_*S_)

// ---------------- device scratch ----------------
__device__ float g_W1[L_*D_*HID_];
__device__ float g_W2[L_*HID_*D_];
__device__ float g_b1[L_*HID_];
__device__ float g_b2[L_*D_];
__device__ float g_h[L_*ND_];
__device__ float g_hmid[L_*ND_];
__device__ float g_hfin[ND_];
__device__ float g_m[L_*ND_];
__device__ float g_qkv[L_*NQ_];
__device__ float g_att[L_*NA_];
__device__ float g_z1[L_*NH1_];
__device__ float g_gl[L_*NH1_];
__device__ float g_abuf[ND_];
__device__ float g_obuf[ND_];
__device__ float g_dh[ND_];
__device__ float g_dtH[NH1_];
__device__ float g_dtD[ND_];
__device__ float g_dob[ND_];
__device__ float g_dqkv[NQ_];
__device__ float g_ds[NA_];
__device__ float g_dlog[NT_*V_];
__device__ float g_rmax[NT_];
__device__ float g_rsum[NT_];
__device__ float g_work[8*1024*1024];     // split-K partials (32 MB)
__device__ unsigned g_cnt[4096];          // per-tile arrival counters (zero-init)

// ---------------- gelu helpers ----------------
__device__ __forceinline__ float gelu_f(float x) {
    float u = 0.7978845608028654f * (x + 0.044715f * x * x * x);
    return 0.5f * x * (1.f + tanhf(u));
}
__device__ __forceinline__ float dgelu_f(float x) {
    float x2 = x * x;
    float u = 0.7978845608028654f * (x + 0.044715f * x * x2);
    float t = tanhf(u);
    return 0.5f * (1.f + t)
         + 0.5f * x * (1.f - t * t) * 0.7978845608028654f * (1.f + 3.f * 0.044715f * x2);
}

// epilogue: mode 0: C = alpha*s + bias? + res? + beta*C
//           mode 1: C = alpha*s + bias; gl = gelu(C)
//           mode 2: C = alpha*s * dgelu(zbuf)
__device__ __forceinline__ void epi_store(
    float s, int grow, int gcol, float alpha, float beta,
    float* __restrict__ C, int ldc,
    const float* __restrict__ bias, const float* __restrict__ res,
    const float* __restrict__ zbuf, float* __restrict__ gl, int mode)
{
    size_t ci = (size_t)grow * ldc + gcol;
    float v = alpha * s;
    if (mode == 1) {
        v += bias[gcol];
        C[ci] = v;
        gl[ci] = gelu_f(v);
    } else if (mode == 2) {
        C[ci] = v * dgelu_f(zbuf[ci]);
    } else {
        if (bias) v += bias[gcol];
        if (res)  v += res[ci];
        if (beta != 0.f) v += beta * C[ci];
        C[ci] = v;
    }
}

// ---------------- 128x128x16 GEMM with fused split-K finalize ----------------
template<int TA, int TB>
__global__ void __launch_bounds__(256) gemm128(
    int M, int N, int K, float alpha,
    const float* __restrict__ A, int lda,
    const float* __restrict__ B, int ldb,
    float beta, float* __restrict__ C, int ldc,
    const float* __restrict__ bias, const float* __restrict__ res,
    const float* __restrict__ zbuf, float* __restrict__ gl, int mode,
    float* __restrict__ work, unsigned* __restrict__ cnt)
{
    __shared__ __align__(16) float As[2][16*128];
    __shared__ __align__(16) float Bs[2][16*128];
    const int tid = threadIdx.x;
    const int m0 = blockIdx.y * 128, n0 = blockIdx.x * 128;
    const int nz = gridDim.z, z = blockIdx.z;
    const int kslice = K / nz, kbeg = z * kslice;

    const int a_r = TA ? (tid >> 4) : (tid >> 1);
    const int a_c = TA ? ((tid & 15) * 8) : ((tid & 1) * 8);
    const int b_r = TB ? (tid >> 1) : (tid >> 4);
    const int b_c = TB ? ((tid & 1) * 8) : ((tid & 15) * 8);

    float4 pa0, pa1, pb0, pb1;

    auto ldg = [&](int kk) {
        const float* pa = TA ? (A + (size_t)(kk + a_r) * lda + m0 + a_c)
                             : (A + (size_t)(m0 + a_r) * lda + kk + a_c);
        pa0 = *(const float4*)pa; pa1 = *(const float4*)(pa + 4);
        const float* pb = TB ? (B + (size_t)(n0 + b_r) * ldb + kk + b_c)
                             : (B + (size_t)(kk + b_r) * ldb + n0 + b_c);
        pb0 = *(const float4*)pb; pb1 = *(const float4*)(pb + 4);
    };
    auto sts = [&](int buf) {
        if (!TA) {
            float va[8] = {pa0.x,pa0.y,pa0.z,pa0.w,pa1.x,pa1.y,pa1.z,pa1.w};
            #pragma unroll
            for (int i = 0; i < 8; i++) As[buf][(a_c + i) * 128 + a_r] = va[i];
        } else {
            *(float4*)&As[buf][a_r * 128 + a_c]     = pa0;
            *(float4*)&As[buf][a_r * 128 + a_c + 4] = pa1;
        }
        if (!TB) {
            *(float4*)&Bs[buf][b_r * 128 + b_c]     = pb0;
            *(float4*)&Bs[buf][b_r * 128 + b_c + 4] = pb1;
        } else {
            float vb[8] = {pb0.x,pb0.y,pb0.z,pb0.w,pb1.x,pb1.y,pb1.z,pb1.w};
            #pragma unroll
            for (int i = 0; i < 8; i++) Bs[buf][(b_c + i) * 128 + b_r] = vb[i];
        }
    };

    float acc[8][8] = {};
    const int ty = tid >> 4, tx = tid & 15;

    ldg(kbeg); sts(0); __syncthreads();
    const int KT = kslice >> 4;
    for (int kt = 0; kt < KT; kt++) {
        int buf = kt & 1;
        if (kt + 1 < KT) ldg(kbeg + (kt + 1) * 16);
        #pragma unroll
        for (int k = 0; k < 16; k++) {
            float4 a0 = *(const float4*)&As[buf][k*128 + ty*8];
            float4 a1 = *(const float4*)&As[buf][k*128 + ty*8 + 4];
            float4 b0 = *(const float4*)&Bs[buf][k*128 + tx*8];
            float4 b1 = *(const float4*)&Bs[buf][k*128 + tx*8 + 4];
            float av[8] = {a0.x,a0.y,a0.z,a0.w,a1.x,a1.y,a1.z,a1.w};
            float bv[8] = {b0.x,b0.y,b0.z,b0.w,b1.x,b1.y,b1.z,b1.w};
            #pragma unroll
            for (int i = 0; i < 8; i++)
                #pragma unroll
                for (int j = 0; j < 8; j++)
                    acc[i][j] += av[i] * bv[j];
        }
        if (kt + 1 < KT) sts(buf ^ 1);
        __syncthreads();
    }

    const int mm = m0 + ty * 8, nn = n0 + tx * 8;

    if (nz == 1) {
        #pragma unroll
        for (int i = 0; i < 8; i++)
            #pragma unroll
            for (int j = 0; j < 8; j++)
                epi_store(acc[i][j], mm + i, nn + j, alpha, beta,
                          C, ldc, bias, res, zbuf, gl, mode);
        return;
    }

    // write raw partials
    const size_t MN = (size_t)M * N;
    float* W = work + (size_t)z * MN;
    #pragma unroll
    for (int i = 0; i < 8; i++) {
        float4 v0 = {acc[i][0], acc[i][1], acc[i][2], acc[i][3]};
        float4 v1 = {acc[i][4], acc[i][5], acc[i][6], acc[i][7]};
        *(float4*)&W[(size_t)(mm + i) * N + nn]     = v0;
        *(float4*)&W[(size_t)(mm + i) * N + nn + 4] = v1;
    }
    __threadfence();

    __shared__ unsigned s_last;
    const int tile = blockIdx.y * gridDim.x + blockIdx.x;
    if (tid == 0) {
        unsigned old = atomicAdd(&cnt[tile], 1u);
        s_last = (old == (unsigned)(nz - 1));
    }
    __syncthreads();
    if (!s_last) return;
    if (tid == 0) cnt[tile] = 0;

    // last block reduces the whole 128x128 tile in fixed z order (deterministic)
    #pragma unroll 1
    for (int kk = 0; kk < 16; kk++) {
        int idx = kk * 1024 + tid * 4;
        int row = idx >> 7, col = idx & 127;
        size_t base = (size_t)(m0 + row) * N + n0 + col;
        float4 s = {0.f, 0.f, 0.f, 0.f};
        for (int zz = 0; zz < nz; zz++) {
            float4 p = *(const float4*)&work[(size_t)zz * MN + base];
            s.x += p.x; s.y += p.y; s.z += p.z; s.w += p.w;
        }
        epi_store(s.x, m0+row, n0+col,   alpha, beta, C, ldc, bias, res, zbuf, gl, mode);
        epi_store(s.y, m0+row, n0+col+1, alpha, beta, C, ldc, bias, res, zbuf, gl, mode);
        epi_store(s.z, m0+row, n0+col+2, alpha, beta, C, ldc, bias, res, zbuf, gl, mode);
        epi_store(s.w, m0+row, n0+col+3, alpha, beta, C, ldc, bias, res, zbuf, gl, mode);
    }
}

// ---------------- misc kernels ----------------
__global__ void __launch_bounds__(256) copy_k(const float* __restrict__ a, float* __restrict__ b) {
    int i = blockIdx.x * 256 + threadIdx.x;
    b[i] = a[i];
}

__global__ void __launch_bounds__(256) embed_k(const int* __restrict__ x,
    const float* __restrict__ emb, const float* __restrict__ pos,
    float* __restrict__ h, int off)
{
    int idx = blockIdx.x * 256 + threadIdx.x;
    int row = idx >> 9, d = idx & 511;
    int b = row >> 7, s = row & 127;
    int tok = x[b * T_ + off + s];
    h[idx] = emb[(size_t)tok * D_ + d] + pos[s * D_ + d];
}

__global__ void __launch_bounds__(256) ln_fwd(const float* __restrict__ x,
    const float* __restrict__ s, const float* __restrict__ b, float* __restrict__ y)
{
    __shared__ float red[256];
    int row = blockIdx.x, tid = threadIdx.x;
    const float* xr = x + (size_t)row * D_;
    float x0 = xr[tid], x1 = xr[tid + 256];
    red[tid] = x0 + x1; __syncthreads();
    for (int w = 128; w > 0; w >>= 1) { if (tid < w) red[tid] += red[tid + w]; __syncthreads(); }
    float mean = red[0] * (1.f / D_); __syncthreads();
    float d0 = x0 - mean, d1 = x1 - mean;
    red[tid] = d0 * d0 + d1 * d1; __syncthreads();
    for (int w = 128; w > 0; w >>= 1) { if (tid < w) red[tid] += red[tid + w]; __syncthreads(); }
    float rstd = rsqrtf(red[0] * (1.f / D_) + 1e-5f);
    float* yr = y + (size_t)row * D_;
    yr[tid]       = d0 * rstd * s[tid]       + b[tid];
    yr[tid + 256] = d1 * rstd * s[tid + 256] + b[tid + 256];
}

__global__ void __launch_bounds__(256) ln_bwd(const float* __restrict__ x,
    const float* __restrict__ dy, const float* __restrict__ s,
    float* __restrict__ dacc, int accum)
{
    __shared__ float red[256];
    int row = blockIdx.x, tid = threadIdx.x;
    const float* xr = x + (size_t)row * D_;
    const float* dr = dy + (size_t)row * D_;
    float x0 = xr[tid], x1 = xr[tid + 256];
    red[tid] = x0 + x1; __syncthreads();
    for (int w = 128; w > 0; w >>= 1) { if (tid < w) red[tid] += red[tid + w]; __syncthreads(); }
    float mean = red[0] * (1.f / D_); __syncthreads();
    float d0 = x0 - mean, d1 = x1 - mean;
    red[tid] = d0 * d0 + d1 * d1; __syncthreads();
    for (int w = 128; w > 0; w >>= 1) { if (tid < w) red[tid] += red[tid + w]; __syncthreads(); }
    float rstd = rsqrtf(red[0] * (1.f / D_) + 1e-5f); __syncthreads();
    float xh0 = d0 * rstd, xh1 = d1 * rstd;
    float g0 = s[tid] * dr[tid], g1 = s[tid + 256] * dr[tid + 256];
    red[tid] = g0 + g1; __syncthreads();
    for (int w = 128; w > 0; w >>= 1) { if (tid < w) red[tid] += red[tid + w]; __syncthreads(); }
    float t1 = red[0] * (1.f / D_); __syncthreads();
    red[tid] = g0 * xh0 + g1 * xh1; __syncthreads();
    for (int w = 128; w > 0; w >>= 1) { if (tid < w) red[tid] += red[tid + w]; __syncthreads(); }
    float t2 = red[0] * (1.f / D_);
    float dx0 = rstd * (g0 - t1 - xh0 * t2);
    float dx1 = rstd * (g1 - t1 - xh1 * t2);
    float* ar = dacc + (size_t)row * D_;
    if (accum) { ar[tid] += dx0; ar[tid + 256] += dx1; }
    else       { ar[tid]  = dx0; ar[tid + 256]  = dx1; }
}

__global__ void __launch_bounds__(128) attn_fwd(const float* __restrict__ qkv,
    float* __restrict__ att, float* __restrict__ obuf)
{
    int qi = blockIdx.x, h = blockIdx.y, b = blockIdx.z, tid = threadIdx.x;
    __shared__ float qs[DH_]; __shared__ float sc[S_]; __shared__ float red[128];
    int row = b * S_ + qi;
    if (tid < DH_) qs[tid] = qkv[(size_t)row * (3*D_) + h * DH_ + tid];
    __syncthreads();
    float sj = -1e30f;
    if (tid <= qi) {
        const float* kp = qkv + (size_t)(b * S_ + tid) * (3*D_) + D_ + h * DH_;
        float a = 0.f;
        #pragma unroll
        for (int d = 0; d < DH_; d++) a += qs[d] * kp[d];
        sj = a * ASC_;
    }
    red[tid] = sj; __syncthreads();
    for (int w = 64; w > 0; w >>= 1) { if (tid < w) red[tid] = fmaxf(red[tid], red[tid + w]); __syncthreads(); }
    float mx = red[0]; __syncthreads();
    float e = (tid <= qi) ? expf(sj - mx) : 0.f;
    red[tid] = e; __syncthreads();
    for (int w = 64; w > 0; w >>= 1) { if (tid < w) red[tid] += red[tid + w]; __syncthreads(); }
    float a = e / red[0];
    size_t arow = ((size_t)(b * NH_ + h) * S_ + qi) * S_;
    att[arow + tid] = a;
    sc[tid] = a; __syncthreads();
    if (tid < DH_) {
        float acc = 0.f;
        for (int j = 0; j <= qi; j++)
            acc += sc[j] * qkv[(size_t)(b * S_ + j) * (3*D_) + 2*D_ + h * DH_ + tid];
        obuf[(size_t)row * D_ + h * DH_ + tid] = acc;
    }
}

__global__ void __launch_bounds__(128) attn_bwd1(const float* __restrict__ qkv,
    const float* __restrict__ att, const float* __restrict__ dob,
    float* __restrict__ dsbuf, float* __restrict__ dqkv)
{
    int qi = blockIdx.x, h = blockIdx.y, b = blockIdx.z, tid = threadIdx.x;
    __shared__ float dov[DH_]; __shared__ float sc[S_]; __shared__ float red[128];
    int row = b * S_ + qi;
    if (tid < DH_) dov[tid] = dob[(size_t)row * D_ + h * DH_ + tid];
    __syncthreads();
    size_t arow = ((size_t)(b * NH_ + h) * S_ + qi) * S_;
    float a = att[arow + tid];
    float datt = 0.f;
    if (tid <= qi) {
        const float* vp = qkv + (size_t)(b * S_ + tid) * (3*D_) + 2*D_ + h * DH_;
        #pragma unroll
        for (int d = 0; d < DH_; d++) datt += dov[d] * vp[d];
    }
    red[tid] = a * datt; __syncthreads();
    for (int w = 64; w > 0; w >>= 1) { if (tid < w) red[tid] += red[tid + w]; __syncthreads(); }
    float tot = red[0];
    float ds = a * (datt - tot);
    dsbuf[arow + tid] = ds;
    sc[tid] = ds; __syncthreads();
    if (tid < DH_) {
        float acc = 0.f;
        for (int j = 0; j <= qi; j++)
            acc += sc[j] * qkv[(size_t)(b * S_ + j) * (3*D_) + D_ + h * DH_ + tid];
        dqkv[(size_t)row * (3*D_) + h * DH_ + tid] = acc * ASC_;
    }
}

__global__ void __launch_bounds__(64) attn_bwd2(const float* __restrict__ qkv,
    const float* __restrict__ att, const float* __restrict__ dob,
    const float* __restrict__ dsbuf, float* __restrict__ dqkv)
{
    int j = blockIdx.x, h = blockIdx.y, b = blockIdx.z, d = threadIdx.x;
    size_t bh = (size_t)(b * NH_ + h) * S_;
    float dk = 0.f, dv = 0.f;
    for (int q = j; q < S_; q++) {
        float ds = dsbuf[(bh + q) * S_ + j];
        float a  = att[(bh + q) * S_ + j];
        dk += ds * qkv[(size_t)(b * S_ + q) * (3*D_) + h * DH_ + d];
        dv += a  * dob[(size_t)(b * S_ + q) * D_ + h * DH_ + d];
    }
    dqkv[(size_t)(b * S_ + j) * (3*D_) + D_   + h * DH_ + d] = dk * ASC_;
    dqkv[(size_t)(b * S_ + j) * (3*D_) + 2*D_ + h * DH_ + d] = dv;
}

__global__ void __launch_bounds__(256) bias_sgd(const float* __restrict__ dY,
    float* __restrict__ bv, int C)
{
    int c = blockIdx.x * 256 + threadIdx.x;
    float s = 0.f;
    for (int i = 0; i < NT_; i++) s += dY[(size_t)i * C + c];
    bv[c] -= LR_ * s;
}

__global__ void __launch_bounds__(256) smax_stats(const float* __restrict__ out, int off,
    float* __restrict__ rmax, float* __restrict__ rsum)
{
    __shared__ float red[256];
    int i = blockIdx.x, tid = threadIdx.x;
    int b = i >> 7, s = i & 127;
    const float* lp = out + ((size_t)(b * (NCH_*S_) + off + s)) * V_;
    float m = -1e30f;
    for (int v = tid; v < V_; v += 256) m = fmaxf(m, lp[v]);
    red[tid] = m; __syncthreads();
    for (int w = 128; w > 0; w >>= 1) { if (tid < w) red[tid] = fmaxf(red[tid], red[tid + w]); __syncthreads(); }
    m = red[0]; __syncthreads();
    float sum = 0.f;
    for (int v = tid; v < V_; v += 256) sum += expf(lp[v] - m);
    red[tid] = sum; __syncthreads();
    for (int w = 128; w > 0; w >>= 1) { if (tid < w) red[tid] += red[tid + w]; __syncthreads(); }
    if (tid == 0) { rmax[i] = m; rsum[i] = red[0]; }
}

__global__ void __launch_bounds__(256) dlogits_k(const float* __restrict__ out,
    const int* __restrict__ x, int off, const float* __restrict__ rmax,
    const float* __restrict__ rsum, float* __restrict__ dl)
{
    int v = blockIdx.x * 256 + threadIdx.x;
    int i = blockIdx.y;
    int b = i >> 7, s = i & 127;
    float l = out[((size_t)(b * (NCH_*S_) + off + s)) * V_ + v];
    float p = expf(l - rmax[i]) / rsum[i];
    int tgt = x[b * T_ + off + s + 1];
    dl[(size_t)i * V_ + v] = (p - (v == tgt ? 1.f : 0.f)) * (1.f / NT_);
}

// ---------------- host ----------------
static float* P(const void* sym) { void* p = 0; cudaGetSymbolAddress(&p, sym); return (float*)p; }

static float* h_work;
static unsigned* h_cnt;

static void gemmx(int TA, int TB, int M, int N, int K, int nz, float alpha,
                  const float* A, int lda, const float* B, int ldb,
                  float beta, float* C, int ldc,
                  const float* bias, const float* res,
                  const float* zbuf, float* gl, int mode)
{
    dim3 g(N / 128, M / 128, nz);
    if (!TA && !TB)      gemm128<0,0><<<g,256>>>(M,N,K,alpha,A,lda,B,ldb,beta,C,ldc,bias,res,zbuf,gl,mode,h_work,h_cnt);
    else if (!TA && TB)  gemm128<0,1><<<g,256>>>(M,N,K,alpha,A,lda,B,ldb,beta,C,ldc,bias,res,zbuf,gl,mode,h_work,h_cnt);
    else if (TA && !TB)  gemm128<1,0><<<g,256>>>(M,N,K,alpha,A,lda,B,ldb,beta,C,ldc,bias,res,zbuf,gl,mode,h_work,h_cnt);
    else                 gemm128<1,1><<<g,256>>>(M,N,K,alpha,A,lda,B,ldb,beta,C,ldc,bias,res,zbuf,gl,mode,h_work,h_cnt);
}

extern "C" void kernel_launch(void* const* d_in, const int* in_sizes, int n_in,
                              void* d_out, int out_size)
{
    const int*   x     = (const int*)  d_in[0];
    const float* emb   = (const float*)d_in[1];
    const float* pos   = (const float*)d_in[2];
    const float* ln1s  = (const float*)d_in[3];
    const float* ln1b  = (const float*)d_in[4];
    const float* Wqkv  = (const float*)d_in[5];
    const float* bqkv  = (const float*)d_in[6];
    const float* Wo    = (const float*)d_in[7];
    const float* bo    = (const float*)d_in[8];
    const float* ln2s  = (const float*)d_in[9];
    const float* ln2b  = (const float*)d_in[10];
    const float* W1i   = (const float*)d_in[11];
    const float* b1i   = (const float*)d_in[12];
    const float* W2i   = (const float*)d_in[13];
    const float* b2i   = (const float*)d_in[14];
    const float* lnfs  = (const float*)d_in[15];
    const float* lnfb  = (const float*)d_in[16];
    const float* Whead = (const float*)d_in[17];
    const float* bhead = (const float*)d_in[18];
    float* out = (float*)d_out;

    float *pW1 = P(g_W1), *pW2 = P(g_W2), *pb1 = P(g_b1), *pb2 = P(g_b2);
    float *ph = P(g_h), *phmid = P(g_hmid), *phfin = P(g_hfin), *pm = P(g_m);
    float *pqkv = P(g_qkv), *patt = P(g_att), *pz1 = P(g_z1), *pgl = P(g_gl);
    float *pabuf = P(g_abuf), *pobuf = P(g_obuf), *pdh = P(g_dh);
    float *pdtH = P(g_dtH), *pdtD = P(g_dtD), *pdob = P(g_dob);
    float *pdqkv = P(g_dqkv), *pds = P(g_ds), *pdlog = P(g_dlog);
    float *prmax = P(g_rmax), *prsum = P(g_rsum);
    h_work = P(g_work);
    { void* p = 0; cudaGetSymbolAddress(&p, g_cnt); h_cnt = (unsigned*)p; }

    copy_k<<<(L_*D_*HID_)/256, 256>>>(W1i, pW1);
    copy_k<<<(L_*HID_*D_)/256, 256>>>(W2i, pW2);
    copy_k<<<(L_*HID_)/256, 256>>>(b1i, pb1);
    copy_k<<<(L_*D_)/256, 256>>>(b2i, pb2);

    for (int c = 0; c < NCH_; c++) {
        const int off = c * S_;

        // ---------------- forward ----------------
        embed_k<<<ND_/256, 256>>>(x, emb, pos, ph, off);
        for (int l = 0; l < L_; l++) {
            float* hin = ph + (size_t)l * ND_;
            float* hmid = phmid + (size_t)l * ND_;
            float* hout = (l < L_-1) ? ph + (size_t)(l+1)*ND_ : phfin;

            ln_fwd<<<NT_, 256>>>(hin, ln1s + l*D_, ln1b + l*D_, pabuf);
            gemmx(0,0, NT_, 3*D_, D_, 8, 1.f, pabuf, D_, Wqkv + (size_t)l*D_*3*D_, 3*D_,
                  0.f, pqkv + (size_t)l*NQ_, 3*D_, bqkv + l*3*D_, 0, 0, 0, 0);
            attn_fwd<<<dim3(S_,NH_,B_), 128>>>(pqkv + (size_t)l*NQ_, patt + (size_t)l*NA_, pobuf);
            gemmx(0,0, NT_, D_, D_, 32, 1.f, pobuf, D_, Wo + (size_t)l*D_*D_, D_,
                  0.f, hmid, D_, bo + l*D_, hin, 0, 0, 0);
            ln_fwd<<<NT_, 256>>>(hmid, ln2s + l*D_, ln2b + l*D_, pm + (size_t)l*ND_);
            gemmx(0,0, NT_, HID_, D_, 8, 1.f, pm + (size_t)l*ND_, D_, pW1 + (size_t)l*D_*HID_, HID_,
                  0.f, pz1 + (size_t)l*NH1_, HID_, pb1 + l*HID_, 0, 0, pgl + (size_t)l*NH1_, 1);
            gemmx(0,0, NT_, D_, HID_, 32, 1.f, pgl + (size_t)l*NH1_, HID_, pW2 + (size_t)l*HID_*D_, D_,
                  0.f, hout, D_, pb2 + l*D_, hmid, 0, 0, 0);
        }
        ln_fwd<<<NT_, 256>>>(phfin, lnfs, lnfb, pabuf);
        for (int b = 0; b < B_; b++)
            gemmx(0,0, S_, V_, D_, 1, 1.f, pabuf + (size_t)b*S_*D_, D_, Whead, V_,
                  0.f, out + ((size_t)(b*(NCH_*S_) + off)) * V_, V_, bhead, 0, 0, 0, 0);

        // ---------------- backward ----------------
        smax_stats<<<NT_, 256>>>(out, off, prmax, prsum);
        dlogits_k<<<dim3(V_/256, NT_), 256>>>(out, x, off, prmax, prsum, pdlog);
        gemmx(0,1, NT_, D_, V_, 25, 1.f, pdlog, V_, Whead, V_, 0.f, pdtD, D_, 0, 0, 0, 0, 0);
        ln_bwd<<<NT_, 256>>>(phfin, pdtD, lnfs, pdh, 0);

        for (int l = L_-1; l >= 0; l--) {
            gemmx(0,1, NT_, HID_, D_, 8, 1.f, pdh, D_, pW2 + (size_t)l*HID_*D_, D_,
                  0.f, pdtH, HID_, 0, 0, pz1 + (size_t)l*NH1_, 0, 2);
            gemmx(1,0, HID_, D_, NT_, 2, -LR_, pgl + (size_t)l*NH1_, HID_, pdh, D_,
                  1.f, pW2 + (size_t)l*HID_*D_, D_, 0, 0, 0, 0, 0);
            bias_sgd<<<D_/256, 256>>>(pdh, pb2 + l*D_, D_);
            gemmx(0,1, NT_, D_, HID_, 32, 1.f, pdtH, HID_, pW1 + (size_t)l*D_*HID_, HID_,
                  0.f, pdtD, D_, 0, 0, 0, 0, 0);
            gemmx(1,0, D_, HID_, NT_, 2, -LR_, pm + (size_t)l*ND_, D_, pdtH, HID_,
                  1.f, pW1 + (size_t)l*D_*HID_, HID_, 0, 0, 0, 0, 0);
            bias_sgd<<<HID_/256, 256>>>(pdtH, pb1 + l*HID_, HID_);
            ln_bwd<<<NT_, 256>>>(phmid + (size_t)l*ND_, pdtD, ln2s + l*D_, pdh, 1);

            gemmx(0,1, NT_, D_, D_, 32, 1.f, pdh, D_, Wo + (size_t)l*D_*D_, D_,
                  0.f, pdob, D_, 0, 0, 0, 0, 0);
            attn_bwd1<<<dim3(S_,NH_,B_), 128>>>(pqkv + (size_t)l*NQ_, patt + (size_t)l*NA_, pdob, pds, pdqkv);
            attn_bwd2<<<dim3(S_,NH_,B_), 64>>>(pqkv + (size_t)l*NQ_, patt + (size_t)l*NA_, pdob, pds, pdqkv);
            gemmx(0,1, NT_, D_, 3*D_, 24, 1.f, pdqkv, 3*D_, Wqkv + (size_t)l*D_*3*D_, 3*D_,
                  0.f, pdtD, D_, 0, 0, 0, 0, 0);
            ln_bwd<<<NT_, 256>>>(ph + (size_t)l*ND_, pdtD, ln1s + l*D_, pdh, 1);
        }
    }
    (void)in_sizes; (void)n_in; (void)out_size;
}

// round 4
// speedup vs baseline: 2.7925x; 2.2559x over previous
#include <cuda_runtime.h>
#include <math.h>

#define D_    512
#define HID_  2048
#define L_    4
#define V_    32000
#define B_    2
#define T_    1025
#define S_    128
#define NH_   8
#define DH_   64
#define NT_   256
#define NCH_  8
#define LR_   0.0003f
#define ASC_  0.125f

#define ND_  (NT_*D_)
#define NH1_ (NT_*HID_)
#define NQ_  (NT_*3*D_)
#define NA_  (B_*NH_*S_*S_)
#define MND_ 131072           // 256*512, MN of all D-output gemms

// ---------------- device scratch ----------------
__device__ float g_W1[L_*D_*HID_];
__device__ float g_W2[L_*HID_*D_];
__device__ float g_b1[L_*HID_];
__device__ float g_b2[L_*D_];
__device__ float g_h[L_*ND_];
__device__ float g_hmid[L_*ND_];
__device__ float g_hfin[ND_];
__device__ float g_m[L_*ND_];
__device__ float g_qkv[L_*NQ_];
__device__ float g_att[L_*NA_];
__device__ float g_z1[L_*NH1_];
__device__ float g_gl[L_*NH1_];
__device__ float g_abuf[ND_];
__device__ float g_obuf[ND_];
__device__ float g_dh[ND_];
__device__ float g_dtH[NH1_];
__device__ float g_dob[ND_];
__device__ float g_dqkv[NQ_];
__device__ float g_ds[NA_];
__device__ float g_dlog[NT_*V_];
__device__ float g_work[8*1024*1024];     // split-K partials (32 MB)

// ---------------- gelu helpers ----------------
__device__ __forceinline__ float gelu_f(float x) {
    float u = 0.7978845608028654f * (x + 0.044715f * x * x * x);
    return 0.5f * x * (1.f + tanhf(u));
}
__device__ __forceinline__ float dgelu_f(float x) {
    float x2 = x * x;
    float u = 0.7978845608028654f * (x + 0.044715f * x * x2);
    float t = tanhf(u);
    return 0.5f * (1.f + t)
         + 0.5f * x * (1.f - t * t) * 0.7978845608028654f * (1.f + 3.f * 0.044715f * x2);
}

// ---------------- 128x128x16 fp32 GEMM (round-2 proven) ----------------
// nz==1: C = alpha*AB + beta*C + bias ; nz>1: work[z] = raw partials
template<int TA, int TB>
__global__ void __launch_bounds__(256) gemm128(
    int M, int N, int K, float alpha,
    const float* __restrict__ A, int lda,
    const float* __restrict__ B, int ldb,
    float beta, float* __restrict__ C, int ldc,
    const float* __restrict__ bias, float* __restrict__ work)
{
    __shared__ __align__(16) float As[2][16*128];
    __shared__ __align__(16) float Bs[2][16*128];
    const int tid = threadIdx.x;
    const int m0 = blockIdx.y * 128, n0 = blockIdx.x * 128;
    const int nz = gridDim.z, z = blockIdx.z;
    const int kslice = K / nz, kbeg = z * kslice;

    const int a_r = TA ? (tid >> 4) : (tid >> 1);
    const int a_c = TA ? ((tid & 15) * 8) : ((tid & 1) * 8);
    const int b_r = TB ? (tid >> 1) : (tid >> 4);
    const int b_c = TB ? ((tid & 1) * 8) : ((tid & 15) * 8);

    float4 pa0, pa1, pb0, pb1;

    auto ldg = [&](int kk) {
        const float* pa = TA ? (A + (size_t)(kk + a_r) * lda + m0 + a_c)
                             : (A + (size_t)(m0 + a_r) * lda + kk + a_c);
        pa0 = *(const float4*)pa; pa1 = *(const float4*)(pa + 4);
        const float* pb = TB ? (B + (size_t)(n0 + b_r) * ldb + kk + b_c)
                             : (B + (size_t)(kk + b_r) * ldb + n0 + b_c);
        pb0 = *(const float4*)pb; pb1 = *(const float4*)(pb + 4);
    };
    auto sts = [&](int buf) {
        if (!TA) {
            float va[8] = {pa0.x,pa0.y,pa0.z,pa0.w,pa1.x,pa1.y,pa1.z,pa1.w};
            #pragma unroll
            for (int i = 0; i < 8; i++) As[buf][(a_c + i) * 128 + a_r] = va[i];
        } else {
            *(float4*)&As[buf][a_r * 128 + a_c]     = pa0;
            *(float4*)&As[buf][a_r * 128 + a_c + 4] = pa1;
        }
        if (!TB) {
            *(float4*)&Bs[buf][b_r * 128 + b_c]     = pb0;
            *(float4*)&Bs[buf][b_r * 128 + b_c + 4] = pb1;
        } else {
            float vb[8] = {pb0.x,pb0.y,pb0.z,pb0.w,pb1.x,pb1.y,pb1.z,pb1.w};
            #pragma unroll
            for (int i = 0; i < 8; i++) Bs[buf][(b_c + i) * 128 + b_r] = vb[i];
        }
    };

    float acc[8][8] = {};
    const int ty = tid >> 4, tx = tid & 15;

    ldg(kbeg); sts(0); __syncthreads();
    const int KT = kslice >> 4;
    for (int kt = 0; kt < KT; kt++) {
        int buf = kt & 1;
        if (kt + 1 < KT) ldg(kbeg + (kt + 1) * 16);
        #pragma unroll
        for (int k = 0; k < 16; k++) {
            float4 a0 = *(const float4*)&As[buf][k*128 + ty*8];
            float4 a1 = *(const float4*)&As[buf][k*128 + ty*8 + 4];
            float4 b0 = *(const float4*)&Bs[buf][k*128 + tx*8];
            float4 b1 = *(const float4*)&Bs[buf][k*128 + tx*8 + 4];
            float av[8] = {a0.x,a0.y,a0.z,a0.w,a1.x,a1.y,a1.z,a1.w};
            float bv[8] = {b0.x,b0.y,b0.z,b0.w,b1.x,b1.y,b1.z,b1.w};
            #pragma unroll
            for (int i = 0; i < 8; i++)
                #pragma unroll
                for (int j = 0; j < 8; j++)
                    acc[i][j] += av[i] * bv[j];
        }
        if (kt + 1 < KT) sts(buf ^ 1);
        __syncthreads();
    }

    const int mm = m0 + ty * 8, nn = n0 + tx * 8;
    if (nz > 1) {
        float* W = work + (size_t)z * M * N;
        #pragma unroll
        for (int i = 0; i < 8; i++) {
            float4 v0 = {acc[i][0], acc[i][1], acc[i][2], acc[i][3]};
            float4 v1 = {acc[i][4], acc[i][5], acc[i][6], acc[i][7]};
            *(float4*)&W[(size_t)(mm + i) * N + nn]     = v0;
            *(float4*)&W[(size_t)(mm + i) * N + nn + 4] = v1;
        }
    } else {
        #pragma unroll
        for (int i = 0; i < 8; i++) {
            float* cp = C + (size_t)(mm + i) * ldc + nn;
            float v[8];
            #pragma unroll
            for (int j = 0; j < 8; j++) {
                v[j] = alpha * acc[i][j];
                if (bias) v[j] += bias[nn + j];
            }
            if (beta != 0.f) {
                #pragma unroll
                for (int j = 0; j < 8; j++) v[j] += beta * cp[j];
            }
            float4 v0 = {v[0], v[1], v[2], v[3]};
            float4 v1 = {v[4], v[5], v[6], v[7]};
            *(float4*)cp = v0; *(float4*)(cp + 4) = v1;
        }
    }
}

// ---------------- split-K reduce (parallel, fused epilogues) ----------------
// mode 0: C = beta*C + alpha*sum + bias?
// mode 1: z = alpha*sum + bias; C = z; gl = gelu(z)
// mode 2: C = alpha*sum * dgelu(zbuf)
__global__ void __launch_bounds__(256) reduce_k(
    const float* __restrict__ work, int nz, int MN, int N,
    float alpha, float beta, float* __restrict__ C,
    const float* __restrict__ bias,
    const float* __restrict__ zbuf, float* __restrict__ gl, int mode)
{
    int i = blockIdx.x * 256 + threadIdx.x;
    float s = 0.f;
    for (int zz = 0; zz < nz; zz++) s += work[(size_t)zz * MN + i];
    s *= alpha;
    if (mode == 1) {
        s += bias[i % N];
        C[i] = s;
        gl[i] = gelu_f(s);
    } else if (mode == 2) {
        C[i] = s * dgelu_f(zbuf[i]);
    } else {
        if (bias) s += bias[i % N];
        if (beta != 0.f) s += beta * C[i];
        C[i] = s;
    }
}

// ---------------- reduce partials + residual + bias, then LayerNorm ----------------
// hout[row] = res[row] + bias + sum_z work ; y[row] = LN(hout[row]) * ls + lb
__global__ void __launch_bounds__(256) reduce_ln(
    const float* __restrict__ work, int nz,
    const float* __restrict__ bias, const float* __restrict__ res,
    float* __restrict__ hout,
    const float* __restrict__ ls, const float* __restrict__ lb,
    float* __restrict__ y)
{
    __shared__ float red[256];
    int row = blockIdx.x, tid = threadIdx.x;
    size_t base = (size_t)row * D_;
    float v0 = 0.f, v1 = 0.f;
    for (int z = 0; z < nz; z++) {
        v0 += work[(size_t)z * MND_ + base + tid];
        v1 += work[(size_t)z * MND_ + base + tid + 256];
    }
    v0 += bias[tid]       + res[base + tid];
    v1 += bias[tid + 256] + res[base + tid + 256];
    hout[base + tid] = v0; hout[base + tid + 256] = v1;

    red[tid] = v0 + v1; __syncthreads();
    for (int w = 128; w > 0; w >>= 1) { if (tid < w) red[tid] += red[tid + w]; __syncthreads(); }
    float mean = red[0] * (1.f / D_); __syncthreads();
    float d0 = v0 - mean, d1 = v1 - mean;
    red[tid] = d0 * d0 + d1 * d1; __syncthreads();
    for (int w = 128; w > 0; w >>= 1) { if (tid < w) red[tid] += red[tid + w]; __syncthreads(); }
    float rstd = rsqrtf(red[0] * (1.f / D_) + 1e-5f);
    y[base + tid]       = d0 * rstd * ls[tid]       + lb[tid];
    y[base + tid + 256] = d1 * rstd * ls[tid + 256] + lb[tid + 256];
}

// ---------------- fused embed + LN1(layer0) ----------------
__global__ void __launch_bounds__(256) embed_ln(const int* __restrict__ x,
    const float* __restrict__ emb, const float* __restrict__ pos, int off,
    float* __restrict__ h, const float* __restrict__ ls, const float* __restrict__ lb,
    float* __restrict__ y)
{
    __shared__ float red[256];
    int row = blockIdx.x, tid = threadIdx.x;
    int b = row >> 7, s = row & 127;
    int tok = x[b * T_ + off + s];
    size_t base = (size_t)row * D_;
    float v0 = emb[(size_t)tok * D_ + tid]       + pos[s * D_ + tid];
    float v1 = emb[(size_t)tok * D_ + tid + 256] + pos[s * D_ + tid + 256];
    h[base + tid] = v0; h[base + tid + 256] = v1;

    red[tid] = v0 + v1; __syncthreads();
    for (int w = 128; w > 0; w >>= 1) { if (tid < w) red[tid] += red[tid + w]; __syncthreads(); }
    float mean = red[0] * (1.f / D_); __syncthreads();
    float d0 = v0 - mean, d1 = v1 - mean;
    red[tid] = d0 * d0 + d1 * d1; __syncthreads();
    for (int w = 128; w > 0; w >>= 1) { if (tid < w) red[tid] += red[tid + w]; __syncthreads(); }
    float rstd = rsqrtf(red[0] * (1.f / D_) + 1e-5f);
    y[base + tid]       = d0 * rstd * ls[tid]       + lb[tid];
    y[base + tid + 256] = d1 * rstd * ls[tid + 256] + lb[tid + 256];
}

// ---------------- LN backward with fused split-K partial sum for dy ----------------
__global__ void __launch_bounds__(256) ln_bwd_f(const float* __restrict__ x,
    const float* __restrict__ work, int nz, const float* __restrict__ s,
    float* __restrict__ dacc, int accum)
{
    __shared__ float red[256];
    int row = blockIdx.x, tid = threadIdx.x;
    size_t base = (size_t)row * D_;
    float dy0 = 0.f, dy1 = 0.f;
    for (int z = 0; z < nz; z++) {
        dy0 += work[(size_t)z * MND_ + base + tid];
        dy1 += work[(size_t)z * MND_ + base + tid + 256];
    }
    float x0 = x[base + tid], x1 = x[base + tid + 256];
    red[tid] = x0 + x1; __syncthreads();
    for (int w = 128; w > 0; w >>= 1) { if (tid < w) red[tid] += red[tid + w]; __syncthreads(); }
    float mean = red[0] * (1.f / D_); __syncthreads();
    float d0 = x0 - mean, d1 = x1 - mean;
    red[tid] = d0 * d0 + d1 * d1; __syncthreads();
    for (int w = 128; w > 0; w >>= 1) { if (tid < w) red[tid] += red[tid + w]; __syncthreads(); }
    float rstd = rsqrtf(red[0] * (1.f / D_) + 1e-5f); __syncthreads();
    float xh0 = d0 * rstd, xh1 = d1 * rstd;
    float g0 = s[tid] * dy0, g1 = s[tid + 256] * dy1;
    red[tid] = g0 + g1; __syncthreads();
    for (int w = 128; w > 0; w >>= 1) { if (tid < w) red[tid] += red[tid + w]; __syncthreads(); }
    float t1 = red[0] * (1.f / D_); __syncthreads();
    red[tid] = g0 * xh0 + g1 * xh1; __syncthreads();
    for (int w = 128; w > 0; w >>= 1) { if (tid < w) red[tid] += red[tid + w]; __syncthreads(); }
    float t2 = red[0] * (1.f / D_);
    float dx0 = rstd * (g0 - t1 - xh0 * t2);
    float dx1 = rstd * (g1 - t1 - xh1 * t2);
    float* ar = dacc + base;
    if (accum) { ar[tid] += dx0; ar[tid + 256] += dx1; }
    else       { ar[tid]  = dx0; ar[tid + 256]  = dx1; }
}

// ---------------- attention forward ----------------
__global__ void __launch_bounds__(128) attn_fwd(const float* __restrict__ qkv,
    float* __restrict__ att, float* __restrict__ obuf)
{
    int qi = blockIdx.x, h = blockIdx.y, b = blockIdx.z, tid = threadIdx.x;
    __shared__ float qs[DH_]; __shared__ float sc[S_]; __shared__ float red[128];
    int row = b * S_ + qi;
    if (tid < DH_) qs[tid] = qkv[(size_t)row * (3*D_) + h * DH_ + tid];
    __syncthreads();
    float sj = -1e30f;
    if (tid <= qi) {
        const float* kp = qkv + (size_t)(b * S_ + tid) * (3*D_) + D_ + h * DH_;
        float a = 0.f;
        #pragma unroll
        for (int d = 0; d < DH_; d++) a += qs[d] * kp[d];
        sj = a * ASC_;
    }
    red[tid] = sj; __syncthreads();
    for (int w = 64; w > 0; w >>= 1) { if (tid < w) red[tid] = fmaxf(red[tid], red[tid + w]); __syncthreads(); }
    float mx = red[0]; __syncthreads();
    float e = (tid <= qi) ? expf(sj - mx) : 0.f;
    red[tid] = e; __syncthreads();
    for (int w = 64; w > 0; w >>= 1) { if (tid < w) red[tid] += red[tid + w]; __syncthreads(); }
    float a = e / red[0];
    size_t arow = ((size_t)(b * NH_ + h) * S_ + qi) * S_;
    att[arow + tid] = a;
    sc[tid] = a; __syncthreads();
    if (tid < DH_) {
        float acc = 0.f;
        for (int j = 0; j <= qi; j++)
            acc += sc[j] * qkv[(size_t)(b * S_ + j) * (3*D_) + 2*D_ + h * DH_ + tid];
        obuf[(size_t)row * D_ + h * DH_ + tid] = acc;
    }
}

// ---------------- attention backward 1 (fused dob partial-sum) ----------------
__global__ void __launch_bounds__(128) attn_bwd1(const float* __restrict__ qkv,
    const float* __restrict__ att, const float* __restrict__ work, int nz,
    float* __restrict__ dob, float* __restrict__ dsbuf, float* __restrict__ dqkv)
{
    int qi = blockIdx.x, h = blockIdx.y, b = blockIdx.z, tid = threadIdx.x;
    __shared__ float dov[DH_]; __shared__ float sc[S_]; __shared__ float red[128];
    int row = b * S_ + qi;
    if (tid < DH_) {
        size_t wi = (size_t)row * D_ + h * DH_ + tid;
        float s = 0.f;
        for (int z = 0; z < nz; z++) s += work[(size_t)z * MND_ + wi];
        dov[tid] = s;
        dob[wi] = s;                 // reduced dob for attn_bwd2
    }
    __syncthreads();
    size_t arow = ((size_t)(b * NH_ + h) * S_ + qi) * S_;
    float a = att[arow + tid];
    float datt = 0.f;
    if (tid <= qi) {
        const float* vp = qkv + (size_t)(b * S_ + tid) * (3*D_) + 2*D_ + h * DH_;
        #pragma unroll
        for (int d = 0; d < DH_; d++) datt += dov[d] * vp[d];
    }
    red[tid] = a * datt; __syncthreads();
    for (int w = 64; w > 0; w >>= 1) { if (tid < w) red[tid] += red[tid + w]; __syncthreads(); }
    float tot = red[0];
    float ds = a * (datt - tot);
    dsbuf[arow + tid] = ds;
    sc[tid] = ds; __syncthreads();
    if (tid < DH_) {
        float acc = 0.f;
        for (int j = 0; j <= qi; j++)
            acc += sc[j] * qkv[(size_t)(b * S_ + j) * (3*D_) + D_ + h * DH_ + tid];
        dqkv[(size_t)row * (3*D_) + h * DH_ + tid] = acc * ASC_;
    }
}

__global__ void __launch_bounds__(64) attn_bwd2(const float* __restrict__ qkv,
    const float* __restrict__ att, const float* __restrict__ dob,
    const float* __restrict__ dsbuf, float* __restrict__ dqkv)
{
    int j = blockIdx.x, h = blockIdx.y, b = blockIdx.z, d = threadIdx.x;
    size_t bh = (size_t)(b * NH_ + h) * S_;
    float dk = 0.f, dv = 0.f;
    for (int q = j; q < S_; q++) {
        float ds = dsbuf[(bh + q) * S_ + j];
        float a  = att[(bh + q) * S_ + j];
        dk += ds * qkv[(size_t)(b * S_ + q) * (3*D_) + h * DH_ + d];
        dv += a  * dob[(size_t)(b * S_ + q) * D_ + h * DH_ + d];
    }
    dqkv[(size_t)(b * S_ + j) * (3*D_) + D_   + h * DH_ + d] = dk * ASC_;
    dqkv[(size_t)(b * S_ + j) * (3*D_) + 2*D_ + h * DH_ + d] = dv;
}

// ---------------- both bias SGD updates in one launch ----------------
__global__ void __launch_bounds__(256) bias2_sgd(const float* __restrict__ dh,
    const float* __restrict__ dtH, float* __restrict__ b2, float* __restrict__ b1)
{
    int c = blockIdx.x * 256 + threadIdx.x;
    if (c < D_) {
        float s = 0.f;
        for (int i = 0; i < NT_; i++) s += dh[(size_t)i * D_ + c];
        b2[c] -= LR_ * s;
    } else {
        int c1 = c - D_;
        float s = 0.f;
        for (int i = 0; i < NT_; i++) s += dtH[(size_t)i * HID_ + c1];
        b1[c1] -= LR_ * s;
    }
}

// ---------------- fused softmax stats + dlogits ----------------
__global__ void __launch_bounds__(256) smax_dlog(const float* __restrict__ out,
    const int* __restrict__ x, int off, float* __restrict__ dl)
{
    __shared__ float red[256];
    int i = blockIdx.x, tid = threadIdx.x;
    int b = i >> 7, s = i & 127;
    const float* lp = out + ((size_t)(b * (NCH_*S_) + off + s)) * V_;
    float m = -1e30f;
    for (int v = tid; v < V_; v += 256) m = fmaxf(m, lp[v]);
    red[tid] = m; __syncthreads();
    for (int w = 128; w > 0; w >>= 1) { if (tid < w) red[tid] = fmaxf(red[tid], red[tid + w]); __syncthreads(); }
    m = red[0]; __syncthreads();
    float sum = 0.f;
    for (int v = tid; v < V_; v += 256) sum += expf(lp[v] - m);
    red[tid] = sum; __syncthreads();
    for (int w = 128; w > 0; w >>= 1) { if (tid < w) red[tid] += red[tid + w]; __syncthreads(); }
    float rinv = 1.f / red[0];
    int tgt = x[b * T_ + off + s + 1];
    float* dlr = dl + (size_t)i * V_;
    for (int v = tid; v < V_; v += 256) {
        float p = expf(lp[v] - m) * rinv;
        dlr[v] = (p - (v == tgt ? 1.f : 0.f)) * (1.f / NT_);
    }
}

// ---------------- segmented param copy (one launch) ----------------
#define NW1_ (L_*D_*HID_)
#define NW2_ (L_*HID_*D_)
#define NB1_ (L_*HID_)
#define NB2_ (L_*D_)
__global__ void __launch_bounds__(256) copy_params(
    const float* __restrict__ w1, const float* __restrict__ w2,
    const float* __restrict__ b1, const float* __restrict__ b2,
    float* __restrict__ pw1, float* __restrict__ pw2,
    float* __restrict__ pb1, float* __restrict__ pb2)
{
    int i = blockIdx.x * 256 + threadIdx.x;
    if (i < NW1_) { pw1[i] = w1[i]; }
    int j = i - NW1_;
    if (j >= 0 && j < NW2_) { pw2[j] = w2[j]; }
    int k = i - NW1_ - NW2_;
    if (k >= 0 && k < NB1_) { pb1[k] = b1[k]; }
    int l = i - NW1_ - NW2_ - NB1_;
    if (l >= 0 && l < NB2_) { pb2[l] = b2[l]; }
}

// ---------------- host ----------------
static float* P(const void* sym) { void* p = 0; cudaGetSymbolAddress(&p, sym); return (float*)p; }

static float* h_work;

static void gemmx(int TA, int TB, int M, int N, int K, int nz, float alpha,
                  const float* A, int lda, const float* B, int ldb,
                  float beta, float* C, int ldc, const float* bias)
{
    dim3 g(N / 128, M / 128, nz);
    if (!TA && !TB)      gemm128<0,0><<<g,256>>>(M,N,K,alpha,A,lda,B,ldb,beta,C,ldc,bias,h_work);
    else if (!TA && TB)  gemm128<0,1><<<g,256>>>(M,N,K,alpha,A,lda,B,ldb,beta,C,ldc,bias,h_work);
    else if (TA && !TB)  gemm128<1,0><<<g,256>>>(M,N,K,alpha,A,lda,B,ldb,beta,C,ldc,bias,h_work);
    else                 gemm128<1,1><<<g,256>>>(M,N,K,alpha,A,lda,B,ldb,beta,C,ldc,bias,h_work);
}

extern "C" void kernel_launch(void* const* d_in, const int* in_sizes, int n_in,
                              void* d_out, int out_size)
{
    const int*   x     = (const int*)  d_in[0];
    const float* emb   = (const float*)d_in[1];
    const float* pos   = (const float*)d_in[2];
    const float* ln1s  = (const float*)d_in[3];
    const float* ln1b  = (const float*)d_in[4];
    const float* Wqkv  = (const float*)d_in[5];
    const float* bqkv  = (const float*)d_in[6];
    const float* Wo    = (const float*)d_in[7];
    const float* bo    = (const float*)d_in[8];
    const float* ln2s  = (const float*)d_in[9];
    const float* ln2b  = (const float*)d_in[10];
    const float* W1i   = (const float*)d_in[11];
    const float* b1i   = (const float*)d_in[12];
    const float* W2i   = (const float*)d_in[13];
    const float* b2i   = (const float*)d_in[14];
    const float* lnfs  = (const float*)d_in[15];
    const float* lnfb  = (const float*)d_in[16];
    const float* Whead = (const float*)d_in[17];
    const float* bhead = (const float*)d_in[18];
    float* out = (float*)d_out;

    float *pW1 = P(g_W1), *pW2 = P(g_W2), *pb1 = P(g_b1), *pb2 = P(g_b2);
    float *ph = P(g_h), *phmid = P(g_hmid), *phfin = P(g_hfin), *pm = P(g_m);
    float *pqkv = P(g_qkv), *patt = P(g_att), *pz1 = P(g_z1), *pgl = P(g_gl);
    float *pabuf = P(g_abuf), *pobuf = P(g_obuf), *pdh = P(g_dh);
    float *pdtH = P(g_dtH), *pdob = P(g_dob);
    float *pdqkv = P(g_dqkv), *pds = P(g_ds), *pdlog = P(g_dlog);
    h_work = P(g_work);

    const int copyN = NW1_ + NW2_ + NB1_ + NB2_;
    copy_params<<<(copyN + 255)/256, 256>>>(W1i, W2i, b1i, b2i, pW1, pW2, pb1, pb2);

    for (int c = 0; c < NCH_; c++) {
        const int off = c * S_;

        // ---------------- forward ----------------
        embed_ln<<<NT_, 256>>>(x, emb, pos, off, ph, ln1s, ln1b, pabuf);
        for (int l = 0; l < L_; l++) {
            float* hin = ph + (size_t)l * ND_;
            float* hmid = phmid + (size_t)l * ND_;
            float* hout = (l < L_-1) ? ph + (size_t)(l+1)*ND_ : phfin;
            const float* nls = (l < L_-1) ? ln1s + (l+1)*D_ : lnfs;
            const float* nlb = (l < L_-1) ? ln1b + (l+1)*D_ : lnfb;

            // qkv = ln1(h) @ Wqkv + bqkv
            gemmx(0,0, NT_, 3*D_, D_, 8, 1.f, pabuf, D_, Wqkv + (size_t)l*D_*3*D_, 3*D_, 0.f, 0, 0, 0);
            reduce_k<<<NQ_/256, 256>>>(h_work, 8, NQ_, 3*D_, 1.f, 0.f,
                                       pqkv + (size_t)l*NQ_, bqkv + l*3*D_, 0, 0, 0);
            attn_fwd<<<dim3(S_,NH_,B_), 128>>>(pqkv + (size_t)l*NQ_, patt + (size_t)l*NA_, pobuf);
            // hmid = hin + obuf@Wo + bo ; m = ln2(hmid)
            gemmx(0,0, NT_, D_, D_, 32, 1.f, pobuf, D_, Wo + (size_t)l*D_*D_, D_, 0.f, 0, 0, 0);
            reduce_ln<<<NT_, 256>>>(h_work, 32, bo + l*D_, hin, hmid,
                                    ln2s + l*D_, ln2b + l*D_, pm + (size_t)l*ND_);
            // z1 = m@W1 + b1 ; gl = gelu(z1)
            gemmx(0,0, NT_, HID_, D_, 8, 1.f, pm + (size_t)l*ND_, D_, pW1 + (size_t)l*D_*HID_, HID_, 0.f, 0, 0, 0);
            reduce_k<<<NH1_/256, 256>>>(h_work, 8, NH1_, HID_, 1.f, 0.f,
                                        pz1 + (size_t)l*NH1_, pb1 + l*HID_, 0,
                                        pgl + (size_t)l*NH1_, 1);
            // hout = hmid + gl@W2 + b2 ; abuf = LN_next(hout)
            gemmx(0,0, NT_, D_, HID_, 32, 1.f, pgl + (size_t)l*NH1_, HID_, pW2 + (size_t)l*HID_*D_, D_, 0.f, 0, 0, 0);
            reduce_ln<<<NT_, 256>>>(h_work, 32, pb2 + l*D_, hmid, hout, nls, nlb, pabuf);
        }
        // logits
        for (int b = 0; b < B_; b++)
            gemmx(0,0, S_, V_, D_, 1, 1.f, pabuf + (size_t)b*S_*D_, D_, Whead, V_,
                  0.f, out + ((size_t)(b*(NCH_*S_) + off)) * V_, V_, bhead);

        // ---------------- backward ----------------
        smax_dlog<<<NT_, 256>>>(out, x, off, pdlog);
        gemmx(0,1, NT_, D_, V_, 25, 1.f, pdlog, V_, Whead, V_, 0.f, 0, 0, 0);
        ln_bwd_f<<<NT_, 256>>>(phfin, h_work, 25, lnfs, pdh, 0);

        for (int l = L_-1; l >= 0; l--) {
            // dtH = (dh @ W2^T) * gelu'(z1)
            gemmx(0,1, NT_, HID_, D_, 8, 1.f, pdh, D_, pW2 + (size_t)l*HID_*D_, D_, 0.f, 0, 0, 0);
            reduce_k<<<NH1_/256, 256>>>(h_work, 8, NH1_, HID_, 1.f, 0.f, pdtH, 0,
                                        pz1 + (size_t)l*NH1_, 0, 2);
            // W2 -= LR * gl^T @ dh
            gemmx(1,0, HID_, D_, NT_, 2, 1.f, pgl + (size_t)l*NH1_, HID_, pdh, D_, 0.f, 0, 0, 0);
            reduce_k<<<(HID_*D_)/256, 256>>>(h_work, 2, HID_*D_, D_, -LR_, 1.f,
                                             pW2 + (size_t)l*HID_*D_, 0, 0, 0, 0);
            // b2, b1 updates (b1 uses dtH which is ready)
            bias2_sgd<<<(D_+HID_)/256, 256>>>(pdh, pdtH, pb2 + l*D_, pb1 + l*HID_);
            // dtD(work) = dtH @ W1^T  (uses pre-update W1), then ln2 bwd accumulates into dh
            gemmx(0,1, NT_, D_, HID_, 32, 1.f, pdtH, HID_, pW1 + (size_t)l*D_*HID_, HID_, 0.f, 0, 0, 0);
            ln_bwd_f<<<NT_, 256>>>(phmid + (size_t)l*ND_, h_work, 32, ln2s + l*D_, pdh, 1);
            // W1 -= LR * m^T @ dtH  (after dtD gemm consumed pre-update W1)
            gemmx(1,0, D_, HID_, NT_, 2, 1.f, pm + (size_t)l*ND_, D_, pdtH, HID_, 0.f, 0, 0, 0);
            reduce_k<<<(D_*HID_)/256, 256>>>(h_work, 2, D_*HID_, HID_, -LR_, 1.f,
                                             pW1 + (size_t)l*D_*HID_, 0, 0, 0, 0);

            // dob(work) = dh @ Wo^T ; attn_bwd1 reduces inline and writes dob
            gemmx(0,1, NT_, D_, D_, 32, 1.f, pdh, D_, Wo + (size_t)l*D_*D_, D_, 0.f, 0, 0, 0);
            attn_bwd1<<<dim3(S_,NH_,B_), 128>>>(pqkv + (size_t)l*NQ_, patt + (size_t)l*NA_,
                                                h_work, 32, pdob, pds, pdqkv);
            attn_bwd2<<<dim3(S_,NH_,B_), 64>>>(pqkv + (size_t)l*NQ_, patt + (size_t)l*NA_,
                                               pdob, pds, pdqkv);
            // dtD(work) = dqkv @ Wqkv^T ; ln1 bwd accumulates into dh
            gemmx(0,1, NT_, D_, 3*D_, 24, 1.f, pdqkv, 3*D_, Wqkv + (size_t)l*D_*3*D_, 3*D_, 0.f, 0, 0, 0);
            ln_bwd_f<<<NT_, 256>>>(ph + (size_t)l*ND_, h_work, 24, ln1s + l*D_, pdh, 1);
        }
    }
    (void)in_sizes; (void)n_in; (void)out_size;
}

// round 5
// speedup vs baseline: 3.9106x; 1.4004x over previous
#include <cuda_runtime.h>
#include <math.h>
#include <stdint.h>

#define D_    512
#define HID_  2048
#define L_    4
#define V_    32000
#define B_    2
#define T_    1025
#define S_    128
#define NH_   8
#define DH_   64
#define NT_   256
#define NCH_  8
#define LR_   0.0003f
#define ASC_  0.125f

#define ND_  (NT_*D_)
#define NH1_ (NT_*HID_)
#define NQ_  (NT_*3*D_)
#define NA_  (B_*NH_*S_*S_)
#define MND_ 131072           // 256*512, MN of all D-output gemms

// ---------------- device scratch ----------------
__device__ float g_W1[L_*D_*HID_];
__device__ float g_W2[L_*HID_*D_];
__device__ float g_b1[L_*HID_];
__device__ float g_b2[L_*D_];
__device__ float g_h[L_*ND_];
__device__ float g_hmid[L_*ND_];
__device__ float g_hfin[ND_];
__device__ float g_m[L_*ND_];
__device__ float g_qkv[L_*NQ_];
__device__ float g_att[L_*NA_];
__device__ float g_z1[L_*NH1_];
__device__ float g_gl[L_*NH1_];
__device__ float g_abuf[ND_];
__device__ float g_obuf[ND_];
__device__ float g_dh[ND_];
__device__ float g_dtH[NH1_];
__device__ float g_dob[ND_];
__device__ float g_dqkv[NQ_];
__device__ float g_ds[NA_];
__device__ float g_dlog[NT_*V_];
__device__ float g_work[8*1024*1024];     // split-K partials (32 MB)

// ---------------- gelu helpers ----------------
__device__ __forceinline__ float gelu_f(float x) {
    float u = 0.7978845608028654f * (x + 0.044715f * x * x * x);
    return 0.5f * x * (1.f + tanhf(u));
}
__device__ __forceinline__ float dgelu_f(float x) {
    float x2 = x * x;
    float u = 0.7978845608028654f * (x + 0.044715f * x * x2);
    float t = tanhf(u);
    return 0.5f * (1.f + t)
         + 0.5f * x * (1.f - t * t) * 0.7978845608028654f * (1.f + 3.f * 0.044715f * x2);
}

__device__ __forceinline__ uint32_t f2tf(float f) {
    uint32_t u;
    asm("cvt.rna.tf32.f32 %0, %1;" : "=r"(u) : "f"(f));
    return u;
}

// ---------------- 128x128x16 tf32 tensor-core GEMM ----------------
// smem tiles stored [k][x] with stride 132 (conflict-free fragment LDS).
// 8 warps: 2 (m) x 4 (n); warp tile 64x32 = 4 m16 x 4 n8 tiles, k8 steps.
// nz==1: C = alpha*AB + beta*C + bias ; nz>1: work[z] = raw partials
#define SSTR 132
template<int TA, int TB>
__global__ void __launch_bounds__(256) gemm128(
    int M, int N, int K, float alpha,
    const float* __restrict__ A, int lda,
    const float* __restrict__ B, int ldb,
    float beta, float* __restrict__ C, int ldc,
    const float* __restrict__ bias, float* __restrict__ work)
{
    __shared__ __align__(16) float As[2][16*SSTR];
    __shared__ __align__(16) float Bs[2][16*SSTR];
    const int tid = threadIdx.x;
    const int m0 = blockIdx.y * 128, n0 = blockIdx.x * 128;
    const int nz = gridDim.z, z = blockIdx.z;
    const int kslice = K / nz, kbeg = z * kslice;

    const int a_r = TA ? (tid >> 4) : (tid >> 1);
    const int a_c = TA ? ((tid & 15) * 8) : ((tid & 1) * 8);
    const int b_r = TB ? (tid >> 1) : (tid >> 4);
    const int b_c = TB ? ((tid & 1) * 8) : ((tid & 15) * 8);

    float4 pa0, pa1, pb0, pb1;

    auto ldg = [&](int kk) {
        const float* pa = TA ? (A + (size_t)(kk + a_r) * lda + m0 + a_c)
                             : (A + (size_t)(m0 + a_r) * lda + kk + a_c);
        pa0 = *(const float4*)pa; pa1 = *(const float4*)(pa + 4);
        const float* pb = TB ? (B + (size_t)(n0 + b_r) * ldb + kk + b_c)
                             : (B + (size_t)(kk + b_r) * ldb + n0 + b_c);
        pb0 = *(const float4*)pb; pb1 = *(const float4*)(pb + 4);
    };
    auto sts = [&](int buf) {
        if (!TA) {
            float va[8] = {pa0.x,pa0.y,pa0.z,pa0.w,pa1.x,pa1.y,pa1.z,pa1.w};
            #pragma unroll
            for (int i = 0; i < 8; i++) As[buf][(a_c + i) * SSTR + a_r] = va[i];
        } else {
            *(float4*)&As[buf][a_r * SSTR + a_c]     = pa0;
            *(float4*)&As[buf][a_r * SSTR + a_c + 4] = pa1;
        }
        if (!TB) {
            *(float4*)&Bs[buf][b_r * SSTR + b_c]     = pb0;
            *(float4*)&Bs[buf][b_r * SSTR + b_c + 4] = pb1;
        } else {
            float vb[8] = {pb0.x,pb0.y,pb0.z,pb0.w,pb1.x,pb1.y,pb1.z,pb1.w};
            #pragma unroll
            for (int i = 0; i < 8; i++) Bs[buf][(b_c + i) * SSTR + b_r] = vb[i];
        }
    };

    const int warp = tid >> 5, lane = tid & 31;
    const int mb = (warp >> 2) * 64;      // warp m base within tile
    const int nb = (warp & 3) * 32;      // warp n base within tile
    const int fr = lane >> 2, fq = lane & 3;

    float acc[4][4][4];
    #pragma unroll
    for (int i = 0; i < 4; i++)
        #pragma unroll
        for (int j = 0; j < 4; j++)
            #pragma unroll
            for (int e = 0; e < 4; e++) acc[i][j][e] = 0.f;

    ldg(kbeg); sts(0); __syncthreads();
    const int KT = kslice >> 4;
    for (int kt = 0; kt < KT; kt++) {
        int buf = kt & 1;
        if (kt + 1 < KT) ldg(kbeg + (kt + 1) * 16);
        #pragma unroll
        for (int ks = 0; ks < 16; ks += 8) {
            uint32_t af[4][4], bf[4][2];
            #pragma unroll
            for (int i = 0; i < 4; i++) {
                const float* ap = &As[buf][(ks + fq) * SSTR + mb + 16*i + fr];
                af[i][0] = f2tf(ap[0]);
                af[i][1] = f2tf(ap[8]);
                af[i][2] = f2tf(ap[4*SSTR]);
                af[i][3] = f2tf(ap[4*SSTR + 8]);
            }
            #pragma unroll
            for (int j = 0; j < 4; j++) {
                const float* bp = &Bs[buf][(ks + fq) * SSTR + nb + 8*j + fr];
                bf[j][0] = f2tf(bp[0]);
                bf[j][1] = f2tf(bp[4*SSTR]);
            }
            #pragma unroll
            for (int i = 0; i < 4; i++)
                #pragma unroll
                for (int j = 0; j < 4; j++)
                    asm volatile(
                        "mma.sync.aligned.m16n8k8.row.col.f32.tf32.tf32.f32 "
                        "{%0,%1,%2,%3}, {%4,%5,%6,%7}, {%8,%9}, {%0,%1,%2,%3};"
                        : "+f"(acc[i][j][0]), "+f"(acc[i][j][1]),
                          "+f"(acc[i][j][2]), "+f"(acc[i][j][3])
                        : "r"(af[i][0]), "r"(af[i][1]), "r"(af[i][2]), "r"(af[i][3]),
                          "r"(bf[j][0]), "r"(bf[j][1]));
        }
        if (kt + 1 < KT) sts(buf ^ 1);
        __syncthreads();
    }

    // epilogue: each (i,j) tile holds (r,2q),(r,2q+1),(r+8,2q),(r+8,2q+1)
    if (nz > 1) {
        float* W = work + (size_t)z * M * N;
        #pragma unroll
        for (int i = 0; i < 4; i++) {
            int row = m0 + mb + 16*i + fr;
            #pragma unroll
            for (int j = 0; j < 4; j++) {
                int col = n0 + nb + 8*j + 2*fq;
                float2 v0 = {acc[i][j][0], acc[i][j][1]};
                float2 v1 = {acc[i][j][2], acc[i][j][3]};
                *(float2*)&W[(size_t)row * N + col]       = v0;
                *(float2*)&W[(size_t)(row + 8) * N + col] = v1;
            }
        }
    } else {
        #pragma unroll
        for (int i = 0; i < 4; i++) {
            int row = m0 + mb + 16*i + fr;
            #pragma unroll
            for (int j = 0; j < 4; j++) {
                int col = n0 + nb + 8*j + 2*fq;
                float v[4];
                #pragma unroll
                for (int e = 0; e < 4; e++) v[e] = alpha * acc[i][j][e];
                if (bias) {
                    float b0 = bias[col], b1 = bias[col + 1];
                    v[0] += b0; v[1] += b1; v[2] += b0; v[3] += b1;
                }
                float* c0 = C + (size_t)row * ldc + col;
                float* c1 = C + (size_t)(row + 8) * ldc + col;
                if (beta != 0.f) {
                    v[0] += beta * c0[0]; v[1] += beta * c0[1];
                    v[2] += beta * c1[0]; v[3] += beta * c1[1];
                }
                float2 v0 = {v[0], v[1]}, v1 = {v[2], v[3]};
                *(float2*)c0 = v0; *(float2*)c1 = v1;
            }
        }
    }
}

// ---------------- split-K reduce (parallel, fused epilogues) ----------------
// mode 0: C = beta*C + alpha*sum + bias?
// mode 1: z = alpha*sum + bias; C = z; gl = gelu(z)
// mode 2: C = alpha*sum * dgelu(zbuf)
__global__ void __launch_bounds__(256) reduce_k(
    const float* __restrict__ work, int nz, int MN, int N,
    float alpha, float beta, float* __restrict__ C,
    const float* __restrict__ bias,
    const float* __restrict__ zbuf, float* __restrict__ gl, int mode)
{
    int i = blockIdx.x * 256 + threadIdx.x;
    float s = 0.f;
    for (int zz = 0; zz < nz; zz++) s += work[(size_t)zz * MN + i];
    s *= alpha;
    if (mode == 1) {
        s += bias[i % N];
        C[i] = s;
        gl[i] = gelu_f(s);
    } else if (mode == 2) {
        C[i] = s * dgelu_f(zbuf[i]);
    } else {
        if (bias) s += bias[i % N];
        if (beta != 0.f) s += beta * C[i];
        C[i] = s;
    }
}

// ---------------- reduce partials + residual + bias, then LayerNorm ----------------
__global__ void __launch_bounds__(256) reduce_ln(
    const float* __restrict__ work, int nz,
    const float* __restrict__ bias, const float* __restrict__ res,
    float* __restrict__ hout,
    const float* __restrict__ ls, const float* __restrict__ lb,
    float* __restrict__ y)
{
    __shared__ float red[256];
    int row = blockIdx.x, tid = threadIdx.x;
    size_t base = (size_t)row * D_;
    float v0 = 0.f, v1 = 0.f;
    for (int z = 0; z < nz; z++) {
        v0 += work[(size_t)z * MND_ + base + tid];
        v1 += work[(size_t)z * MND_ + base + tid + 256];
    }
    v0 += bias[tid]       + res[base + tid];
    v1 += bias[tid + 256] + res[base + tid + 256];
    hout[base + tid] = v0; hout[base + tid + 256] = v1;

    red[tid] = v0 + v1; __syncthreads();
    for (int w = 128; w > 0; w >>= 1) { if (tid < w) red[tid] += red[tid + w]; __syncthreads(); }
    float mean = red[0] * (1.f / D_); __syncthreads();
    float d0 = v0 - mean, d1 = v1 - mean;
    red[tid] = d0 * d0 + d1 * d1; __syncthreads();
    for (int w = 128; w > 0; w >>= 1) { if (tid < w) red[tid] += red[tid + w]; __syncthreads(); }
    float rstd = rsqrtf(red[0] * (1.f / D_) + 1e-5f);
    y[base + tid]       = d0 * rstd * ls[tid]       + lb[tid];
    y[base + tid + 256] = d1 * rstd * ls[tid + 256] + lb[tid + 256];
}

// ---------------- fused embed + LN1(layer0) ----------------
__global__ void __launch_bounds__(256) embed_ln(const int* __restrict__ x,
    const float* __restrict__ emb, const float* __restrict__ pos, int off,
    float* __restrict__ h, const float* __restrict__ ls, const float* __restrict__ lb,
    float* __restrict__ y)
{
    __shared__ float red[256];
    int row = blockIdx.x, tid = threadIdx.x;
    int b = row >> 7, s = row & 127;
    int tok = x[b * T_ + off + s];
    size_t base = (size_t)row * D_;
    float v0 = emb[(size_t)tok * D_ + tid]       + pos[s * D_ + tid];
    float v1 = emb[(size_t)tok * D_ + tid + 256] + pos[s * D_ + tid + 256];
    h[base + tid] = v0; h[base + tid + 256] = v1;

    red[tid] = v0 + v1; __syncthreads();
    for (int w = 128; w > 0; w >>= 1) { if (tid < w) red[tid] += red[tid + w]; __syncthreads(); }
    float mean = red[0] * (1.f / D_); __syncthreads();
    float d0 = v0 - mean, d1 = v1 - mean;
    red[tid] = d0 * d0 + d1 * d1; __syncthreads();
    for (int w = 128; w > 0; w >>= 1) { if (tid < w) red[tid] += red[tid + w]; __syncthreads(); }
    float rstd = rsqrtf(red[0] * (1.f / D_) + 1e-5f);
    y[base + tid]       = d0 * rstd * ls[tid]       + lb[tid];
    y[base + tid + 256] = d1 * rstd * ls[tid + 256] + lb[tid + 256];
}

// ---------------- LN backward with fused split-K partial sum for dy ----------------
__global__ void __launch_bounds__(256) ln_bwd_f(const float* __restrict__ x,
    const float* __restrict__ work, int nz, const float* __restrict__ s,
    float* __restrict__ dacc, int accum)
{
    __shared__ float red[256];
    int row = blockIdx.x, tid = threadIdx.x;
    size_t base = (size_t)row * D_;
    float dy0 = 0.f, dy1 = 0.f;
    for (int z = 0; z < nz; z++) {
        dy0 += work[(size_t)z * MND_ + base + tid];
        dy1 += work[(size_t)z * MND_ + base + tid + 256];
    }
    float x0 = x[base + tid], x1 = x[base + tid + 256];
    red[tid] = x0 + x1; __syncthreads();
    for (int w = 128; w > 0; w >>= 1) { if (tid < w) red[tid] += red[tid + w]; __syncthreads(); }
    float mean = red[0] * (1.f / D_); __syncthreads();
    float d0 = x0 - mean, d1 = x1 - mean;
    red[tid] = d0 * d0 + d1 * d1; __syncthreads();
    for (int w = 128; w > 0; w >>= 1) { if (tid < w) red[tid] += red[tid + w]; __syncthreads(); }
    float rstd = rsqrtf(red[0] * (1.f / D_) + 1e-5f); __syncthreads();
    float xh0 = d0 * rstd, xh1 = d1 * rstd;
    float g0 = s[tid] * dy0, g1 = s[tid + 256] * dy1;
    red[tid] = g0 + g1; __syncthreads();
    for (int w = 128; w > 0; w >>= 1) { if (tid < w) red[tid] += red[tid + w]; __syncthreads(); }
    float t1 = red[0] * (1.f / D_); __syncthreads();
    red[tid] = g0 * xh0 + g1 * xh1; __syncthreads();
    for (int w = 128; w > 0; w >>= 1) { if (tid < w) red[tid] += red[tid + w]; __syncthreads(); }
    float t2 = red[0] * (1.f / D_);
    float dx0 = rstd * (g0 - t1 - xh0 * t2);
    float dx1 = rstd * (g1 - t1 - xh1 * t2);
    float* ar = dacc + base;
    if (accum) { ar[tid] += dx0; ar[tid + 256] += dx1; }
    else       { ar[tid]  = dx0; ar[tid + 256]  = dx1; }
}

// ---------------- attention forward ----------------
__global__ void __launch_bounds__(128) attn_fwd(const float* __restrict__ qkv,
    float* __restrict__ att, float* __restrict__ obuf)
{
    int qi = blockIdx.x, h = blockIdx.y, b = blockIdx.z, tid = threadIdx.x;
    __shared__ float qs[DH_]; __shared__ float sc[S_]; __shared__ float red[128];
    int row = b * S_ + qi;
    if (tid < DH_) qs[tid] = qkv[(size_t)row * (3*D_) + h * DH_ + tid];
    __syncthreads();
    float sj = -1e30f;
    if (tid <= qi) {
        const float* kp = qkv + (size_t)(b * S_ + tid) * (3*D_) + D_ + h * DH_;
        float a = 0.f;
        #pragma unroll
        for (int d = 0; d < DH_; d++) a += qs[d] * kp[d];
        sj = a * ASC_;
    }
    red[tid] = sj; __syncthreads();
    for (int w = 64; w > 0; w >>= 1) { if (tid < w) red[tid] = fmaxf(red[tid], red[tid + w]); __syncthreads(); }
    float mx = red[0]; __syncthreads();
    float e = (tid <= qi) ? expf(sj - mx) : 0.f;
    red[tid] = e; __syncthreads();
    for (int w = 64; w > 0; w >>= 1) { if (tid < w) red[tid] += red[tid + w]; __syncthreads(); }
    float a = e / red[0];
    size_t arow = ((size_t)(b * NH_ + h) * S_ + qi) * S_;
    att[arow + tid] = a;
    sc[tid] = a; __syncthreads();
    if (tid < DH_) {
        float acc = 0.f;
        for (int j = 0; j <= qi; j++)
            acc += sc[j] * qkv[(size_t)(b * S_ + j) * (3*D_) + 2*D_ + h * DH_ + tid];
        obuf[(size_t)row * D_ + h * DH_ + tid] = acc;
    }
}

// ---------------- attention backward 1 (fused dob partial-sum) ----------------
__global__ void __launch_bounds__(128) attn_bwd1(const float* __restrict__ qkv,
    const float* __restrict__ att, const float* __restrict__ work, int nz,
    float* __restrict__ dob, float* __restrict__ dsbuf, float* __restrict__ dqkv)
{
    int qi = blockIdx.x, h = blockIdx.y, b = blockIdx.z, tid = threadIdx.x;
    __shared__ float dov[DH_]; __shared__ float sc[S_]; __shared__ float red[128];
    int row = b * S_ + qi;
    if (tid < DH_) {
        size_t wi = (size_t)row * D_ + h * DH_ + tid;
        float s = 0.f;
        for (int z = 0; z < nz; z++) s += work[(size_t)z * MND_ + wi];
        dov[tid] = s;
        dob[wi] = s;
    }
    __syncthreads();
    size_t arow = ((size_t)(b * NH_ + h) * S_ + qi) * S_;
    float a = att[arow + tid];
    float datt = 0.f;
    if (tid <= qi) {
        const float* vp = qkv + (size_t)(b * S_ + tid) * (3*D_) + 2*D_ + h * DH_;
        #pragma unroll
        for (int d = 0; d < DH_; d++) datt += dov[d] * vp[d];
    }
    red[tid] = a * datt; __syncthreads();
    for (int w = 64; w > 0; w >>= 1) { if (tid < w) red[tid] += red[tid + w]; __syncthreads(); }
    float tot = red[0];
    float ds = a * (datt - tot);
    dsbuf[arow + tid] = ds;
    sc[tid] = ds; __syncthreads();
    if (tid < DH_) {
        float acc = 0.f;
        for (int j = 0; j <= qi; j++)
            acc += sc[j] * qkv[(size_t)(b * S_ + j) * (3*D_) + D_ + h * DH_ + tid];
        dqkv[(size_t)row * (3*D_) + h * DH_ + tid] = acc * ASC_;
    }
}

__global__ void __launch_bounds__(64) attn_bwd2(const float* __restrict__ qkv,
    const float* __restrict__ att, const float* __restrict__ dob,
    const float* __restrict__ dsbuf, float* __restrict__ dqkv)
{
    int j = blockIdx.x, h = blockIdx.y, b = blockIdx.z, d = threadIdx.x;
    size_t bh = (size_t)(b * NH_ + h) * S_;
    float dk = 0.f, dv = 0.f;
    for (int q = j; q < S_; q++) {
        float ds = dsbuf[(bh + q) * S_ + j];
        float a  = att[(bh + q) * S_ + j];
        dk += ds * qkv[(size_t)(b * S_ + q) * (3*D_) + h * DH_ + d];
        dv += a  * dob[(size_t)(b * S_ + q) * D_ + h * DH_ + d];
    }
    dqkv[(size_t)(b * S_ + j) * (3*D_) + D_   + h * DH_ + d] = dk * ASC_;
    dqkv[(size_t)(b * S_ + j) * (3*D_) + 2*D_ + h * DH_ + d] = dv;
}

// ---------------- both bias SGD updates in one launch ----------------
__global__ void __launch_bounds__(256) bias2_sgd(const float* __restrict__ dh,
    const float* __restrict__ dtH, float* __restrict__ b2, float* __restrict__ b1)
{
    int c = blockIdx.x * 256 + threadIdx.x;
    if (c < D_) {
        float s = 0.f;
        for (int i = 0; i < NT_; i++) s += dh[(size_t)i * D_ + c];
        b2[c] -= LR_ * s;
    } else {
        int c1 = c - D_;
        float s = 0.f;
        for (int i = 0; i < NT_; i++) s += dtH[(size_t)i * HID_ + c1];
        b1[c1] -= LR_ * s;
    }
}

// ---------------- fused softmax stats + dlogits ----------------
__global__ void __launch_bounds__(256) smax_dlog(const float* __restrict__ out,
    const int* __restrict__ x, int off, float* __restrict__ dl)
{
    __shared__ float red[256];
    int i = blockIdx.x, tid = threadIdx.x;
    int b = i >> 7, s = i & 127;
    const float* lp = out + ((size_t)(b * (NCH_*S_) + off + s)) * V_;
    float m = -1e30f;
    for (int v = tid; v < V_; v += 256) m = fmaxf(m, lp[v]);
    red[tid] = m; __syncthreads();
    for (int w = 128; w > 0; w >>= 1) { if (tid < w) red[tid] = fmaxf(red[tid], red[tid + w]); __syncthreads(); }
    m = red[0]; __syncthreads();
    float sum = 0.f;
    for (int v = tid; v < V_; v += 256) sum += expf(lp[v] - m);
    red[tid] = sum; __syncthreads();
    for (int w = 128; w > 0; w >>= 1) { if (tid < w) red[tid] += red[tid + w]; __syncthreads(); }
    float rinv = 1.f / red[0];
    int tgt = x[b * T_ + off + s + 1];
    float* dlr = dl + (size_t)i * V_;
    for (int v = tid; v < V_; v += 256) {
        float p = expf(lp[v] - m) * rinv;
        dlr[v] = (p - (v == tgt ? 1.f : 0.f)) * (1.f / NT_);
    }
}

// ---------------- segmented param copy (one launch) ----------------
#define NW1_ (L_*D_*HID_)
#define NW2_ (L_*HID_*D_)
#define NB1_ (L_*HID_)
#define NB2_ (L_*D_)
__global__ void __launch_bounds__(256) copy_params(
    const float* __restrict__ w1, const float* __restrict__ w2,
    const float* __restrict__ b1, const float* __restrict__ b2,
    float* __restrict__ pw1, float* __restrict__ pw2,
    float* __restrict__ pb1, float* __restrict__ pb2)
{
    int i = blockIdx.x * 256 + threadIdx.x;
    if (i < NW1_) { pw1[i] = w1[i]; }
    int j = i - NW1_;
    if (j >= 0 && j < NW2_) { pw2[j] = w2[j]; }
    int k = i - NW1_ - NW2_;
    if (k >= 0 && k < NB1_) { pb1[k] = b1[k]; }
    int l = i - NW1_ - NW2_ - NB1_;
    if (l >= 0 && l < NB2_) { pb2[l] = b2[l]; }
}

// ---------------- host ----------------
static float* P(const void* sym) { void* p = 0; cudaGetSymbolAddress(&p, sym); return (float*)p; }

static float* h_work;

static void gemmx(int TA, int TB, int M, int N, int K, int nz, float alpha,
                  const float* A, int lda, const float* B, int ldb,
                  float beta, float* C, int ldc, const float* bias)
{
    dim3 g(N / 128, M / 128, nz);
    if (!TA && !TB)      gemm128<0,0><<<g,256>>>(M,N,K,alpha,A,lda,B,ldb,beta,C,ldc,bias,h_work);
    else if (!TA && TB)  gemm128<0,1><<<g,256>>>(M,N,K,alpha,A,lda,B,ldb,beta,C,ldc,bias,h_work);
    else if (TA && !TB)  gemm128<1,0><<<g,256>>>(M,N,K,alpha,A,lda,B,ldb,beta,C,ldc,bias,h_work);
    else                 gemm128<1,1><<<g,256>>>(M,N,K,alpha,A,lda,B,ldb,beta,C,ldc,bias,h_work);
}

extern "C" void kernel_launch(void* const* d_in, const int* in_sizes, int n_in,
                              void* d_out, int out_size)
{
    const int*   x     = (const int*)  d_in[0];
    const float* emb   = (const float*)d_in[1];
    const float* pos   = (const float*)d_in[2];
    const float* ln1s  = (const float*)d_in[3];
    const float* ln1b  = (const float*)d_in[4];
    const float* Wqkv  = (const float*)d_in[5];
    const float* bqkv  = (const float*)d_in[6];
    const float* Wo    = (const float*)d_in[7];
    const float* bo    = (const float*)d_in[8];
    const float* ln2s  = (const float*)d_in[9];
    const float* ln2b  = (const float*)d_in[10];
    const float* W1i   = (const float*)d_in[11];
    const float* b1i   = (const float*)d_in[12];
    const float* W2i   = (const float*)d_in[13];
    const float* b2i   = (const float*)d_in[14];
    const float* lnfs  = (const float*)d_in[15];
    const float* lnfb  = (const float*)d_in[16];
    const float* Whead = (const float*)d_in[17];
    const float* bhead = (const float*)d_in[18];
    float* out = (float*)d_out;

    float *pW1 = P(g_W1), *pW2 = P(g_W2), *pb1 = P(g_b1), *pb2 = P(g_b2);
    float *ph = P(g_h), *phmid = P(g_hmid), *phfin = P(g_hfin), *pm = P(g_m);
    float *pqkv = P(g_qkv), *patt = P(g_att), *pz1 = P(g_z1), *pgl = P(g_gl);
    float *pabuf = P(g_abuf), *pobuf = P(g_obuf), *pdh = P(g_dh);
    float *pdtH = P(g_dtH), *pdob = P(g_dob);
    float *pdqkv = P(g_dqkv), *pds = P(g_ds), *pdlog = P(g_dlog);
    h_work = P(g_work);

    const int copyN = NW1_ + NW2_ + NB1_ + NB2_;
    copy_params<<<(copyN + 255)/256, 256>>>(W1i, W2i, b1i, b2i, pW1, pW2, pb1, pb2);

    for (int c = 0; c < NCH_; c++) {
        const int off = c * S_;

        // ---------------- forward ----------------
        embed_ln<<<NT_, 256>>>(x, emb, pos, off, ph, ln1s, ln1b, pabuf);
        for (int l = 0; l < L_; l++) {
            float* hin = ph + (size_t)l * ND_;
            float* hmid = phmid + (size_t)l * ND_;
            float* hout = (l < L_-1) ? ph + (size_t)(l+1)*ND_ : phfin;
            const float* nls = (l < L_-1) ? ln1s + (l+1)*D_ : lnfs;
            const float* nlb = (l < L_-1) ? ln1b + (l+1)*D_ : lnfb;

            gemmx(0,0, NT_, 3*D_, D_, 8, 1.f, pabuf, D_, Wqkv + (size_t)l*D_*3*D_, 3*D_, 0.f, 0, 0, 0);
            reduce_k<<<NQ_/256, 256>>>(h_work, 8, NQ_, 3*D_, 1.f, 0.f,
                                       pqkv + (size_t)l*NQ_, bqkv + l*3*D_, 0, 0, 0);
            attn_fwd<<<dim3(S_,NH_,B_), 128>>>(pqkv + (size_t)l*NQ_, patt + (size_t)l*NA_, pobuf);
            gemmx(0,0, NT_, D_, D_, 32, 1.f, pobuf, D_, Wo + (size_t)l*D_*D_, D_, 0.f, 0, 0, 0);
            reduce_ln<<<NT_, 256>>>(h_work, 32, bo + l*D_, hin, hmid,
                                    ln2s + l*D_, ln2b + l*D_, pm + (size_t)l*ND_);
            gemmx(0,0, NT_, HID_, D_, 8, 1.f, pm + (size_t)l*ND_, D_, pW1 + (size_t)l*D_*HID_, HID_, 0.f, 0, 0, 0);
            reduce_k<<<NH1_/256, 256>>>(h_work, 8, NH1_, HID_, 1.f, 0.f,
                                        pz1 + (size_t)l*NH1_, pb1 + l*HID_, 0,
                                        pgl + (size_t)l*NH1_, 1);
            gemmx(0,0, NT_, D_, HID_, 32, 1.f, pgl + (size_t)l*NH1_, HID_, pW2 + (size_t)l*HID_*D_, D_, 0.f, 0, 0, 0);
            reduce_ln<<<NT_, 256>>>(h_work, 32, pb2 + l*D_, hmid, hout, nls, nlb, pabuf);
        }
        for (int b = 0; b < B_; b++)
            gemmx(0,0, S_, V_, D_, 1, 1.f, pabuf + (size_t)b*S_*D_, D_, Whead, V_,
                  0.f, out + ((size_t)(b*(NCH_*S_) + off)) * V_, V_, bhead);

        // ---------------- backward ----------------
        smax_dlog<<<NT_, 256>>>(out, x, off, pdlog);
        gemmx(0,1, NT_, D_, V_, 25, 1.f, pdlog, V_, Whead, V_, 0.f, 0, 0, 0);
        ln_bwd_f<<<NT_, 256>>>(phfin, h_work, 25, lnfs, pdh, 0);

        for (int l = L_-1; l >= 0; l--) {
            gemmx(0,1, NT_, HID_, D_, 8, 1.f, pdh, D_, pW2 + (size_t)l*HID_*D_, D_, 0.f, 0, 0, 0);
            reduce_k<<<NH1_/256, 256>>>(h_work, 8, NH1_, HID_, 1.f, 0.f, pdtH, 0,
                                        pz1 + (size_t)l*NH1_, 0, 2);
            gemmx(1,0, HID_, D_, NT_, 2, 1.f, pgl + (size_t)l*NH1_, HID_, pdh, D_, 0.f, 0, 0, 0);
            reduce_k<<<(HID_*D_)/256, 256>>>(h_work, 2, HID_*D_, D_, -LR_, 1.f,
                                             pW2 + (size_t)l*HID_*D_, 0, 0, 0, 0);
            bias2_sgd<<<(D_+HID_)/256, 256>>>(pdh, pdtH, pb2 + l*D_, pb1 + l*HID_);
            gemmx(0,1, NT_, D_, HID_, 32, 1.f, pdtH, HID_, pW1 + (size_t)l*D_*HID_, HID_, 0.f, 0, 0, 0);
            ln_bwd_f<<<NT_, 256>>>(phmid + (size_t)l*ND_, h_work, 32, ln2s + l*D_, pdh, 1);
            gemmx(1,0, D_, HID_, NT_, 2, 1.f, pm + (size_t)l*ND_, D_, pdtH, HID_, 0.f, 0, 0, 0);
            reduce_k<<<(D_*HID_)/256, 256>>>(h_work, 2, D_*HID_, HID_, -LR_, 1.f,
                                             pW1 + (size_t)l*D_*HID_, 0, 0, 0, 0);

            gemmx(0,1, NT_, D_, D_, 32, 1.f, pdh, D_, Wo + (size_t)l*D_*D_, D_, 0.f, 0, 0, 0);
            attn_bwd1<<<dim3(S_,NH_,B_), 128>>>(pqkv + (size_t)l*NQ_, patt + (size_t)l*NA_,
                                                h_work, 32, pdob, pds, pdqkv);
            attn_bwd2<<<dim3(S_,NH_,B_), 64>>>(pqkv + (size_t)l*NQ_, patt + (size_t)l*NA_,
                                               pdob, pds, pdqkv);
            gemmx(0,1, NT_, D_, 3*D_, 24, 1.f, pdqkv, 3*D_, Wqkv + (size_t)l*D_*3*D_, 3*D_, 0.f, 0, 0, 0);
            ln_bwd_f<<<NT_, 256>>>(ph + (size_t)l*ND_, h_work, 24, ln1s + l*D_, pdh, 1);
        }
    }
    (void)in_sizes; (void)n_in; (void)out_size;
}

// round 6
// speedup vs baseline: 3.9242x; 1.0035x over previous
#include <cuda_runtime.h>
#include <math.h>
#include <stdint.h>

#define D_    512
#define HID_  2048
#define L_    4
#define V_    32000
#define B_    2
#define T_    1025
#define S_    128
#define NH_   8
#define DH_   64
#define NT_   256
#define NCH_  8
#define LR_   0.0003f
#define ASC_  0.125f

#define ND_  (NT_*D_)
#define NH1_ (NT_*HID_)
#define NQ_  (NT_*3*D_)
#define NA_  (B_*NH_*S_*S_)
#define MND_ 131072           // 256*512

// ---------------- device scratch ----------------
__device__ float g_W1[L_*D_*HID_];
__device__ float g_W2[L_*HID_*D_];
__device__ float g_b1[L_*HID_];
__device__ float g_b2[L_*D_];
__device__ float g_h[L_*ND_];
__device__ float g_hmid[L_*ND_];
__device__ float g_hfin[ND_];
__device__ float g_m[L_*ND_];
__device__ float g_qkv[L_*NQ_];
__device__ float g_att[L_*NA_];
__device__ float g_z1[L_*NH1_];
__device__ float g_gl[L_*NH1_];
__device__ float g_abuf[ND_];
__device__ float g_obuf[ND_];
__device__ float g_dh[ND_];
__device__ float g_dtH[NH1_];
__device__ float g_dob[ND_];
__device__ float g_dqkv[NQ_];
__device__ float g_ds[NA_];
__device__ float g_dlog[NT_*V_];
__device__ float g_work[8*1024*1024];     // split-K partials (32 MB)

// ---------------- gelu helpers ----------------
__device__ __forceinline__ float gelu_f(float x) {
    float u = 0.7978845608028654f * (x + 0.044715f * x * x * x);
    return 0.5f * x * (1.f + tanhf(u));
}
__device__ __forceinline__ float dgelu_f(float x) {
    float x2 = x * x;
    float u = 0.7978845608028654f * (x + 0.044715f * x * x2);
    float t = tanhf(u);
    return 0.5f * (1.f + t)
         + 0.5f * x * (1.f - t * t) * 0.7978845608028654f * (1.f + 3.f * 0.044715f * x2);
}

__device__ __forceinline__ uint32_t f2tf(float f) {
    uint32_t u;
    asm("cvt.rna.tf32.f32 %0, %1;" : "=r"(u) : "f"(f));
    return u;
}

// ---------------- 128x128x16 tf32 tensor-core GEMM ----------------
// batched==0: gridDim.z = split-K count (nz>1 -> raw partials to work)
// batched==1: gridDim.z = batch index; full K; C/A offset by z strides
#define SSTR 132
template<int TA, int TB>
__global__ void __launch_bounds__(256) gemm128(
    int M, int N, int K, float alpha,
    const float* __restrict__ A, int lda,
    const float* __restrict__ B, int ldb,
    float beta, float* __restrict__ C, int ldc,
    const float* __restrict__ bias, float* __restrict__ work,
    int batched, size_t sAz, size_t sCz)
{
    __shared__ __align__(16) float As[2][16*SSTR];
    __shared__ __align__(16) float Bs[2][16*SSTR];
    const int tid = threadIdx.x;
    const int m0 = blockIdx.y * 128, n0 = blockIdx.x * 128;
    const int z = blockIdx.z;
    const int nz = batched ? 1 : gridDim.z;
    const int kslice = batched ? K : (K / gridDim.z);
    const int kbeg = batched ? 0 : z * kslice;
    if (batched) { A += (size_t)z * sAz; C += (size_t)z * sCz; }

    const int a_r = TA ? (tid >> 4) : (tid >> 1);
    const int a_c = TA ? ((tid & 15) * 8) : ((tid & 1) * 8);
    const int b_r = TB ? (tid >> 1) : (tid >> 4);
    const int b_c = TB ? ((tid & 1) * 8) : ((tid & 15) * 8);

    float4 pa0, pa1, pb0, pb1;

    auto ldg = [&](int kk) {
        const float* pa = TA ? (A + (size_t)(kk + a_r) * lda + m0 + a_c)
                             : (A + (size_t)(m0 + a_r) * lda + kk + a_c);
        pa0 = *(const float4*)pa; pa1 = *(const float4*)(pa + 4);
        const float* pb = TB ? (B + (size_t)(n0 + b_r) * ldb + kk + b_c)
                             : (B + (size_t)(kk + b_r) * ldb + n0 + b_c);
        pb0 = *(const float4*)pb; pb1 = *(const float4*)(pb + 4);
    };
    auto sts = [&](int buf) {
        if (!TA) {
            float va[8] = {pa0.x,pa0.y,pa0.z,pa0.w,pa1.x,pa1.y,pa1.z,pa1.w};
            #pragma unroll
            for (int i = 0; i < 8; i++) As[buf][(a_c + i) * SSTR + a_r] = va[i];
        } else {
            *(float4*)&As[buf][a_r * SSTR + a_c]     = pa0;
            *(float4*)&As[buf][a_r * SSTR + a_c + 4] = pa1;
        }
        if (!TB) {
            *(float4*)&Bs[buf][b_r * SSTR + b_c]     = pb0;
            *(float4*)&Bs[buf][b_r * SSTR + b_c + 4] = pb1;
        } else {
            float vb[8] = {pb0.x,pb0.y,pb0.z,pb0.w,pb1.x,pb1.y,pb1.z,pb1.w};
            #pragma unroll
            for (int i = 0; i < 8; i++) Bs[buf][(b_c + i) * SSTR + b_r] = vb[i];
        }
    };

    const int warp = tid >> 5, lane = tid & 31;
    const int mb = (warp >> 2) * 64;
    const int nb = (warp & 3) * 32;
    const int fr = lane >> 2, fq = lane & 3;

    float acc[4][4][4];
    #pragma unroll
    for (int i = 0; i < 4; i++)
        #pragma unroll
        for (int j = 0; j < 4; j++)
            #pragma unroll
            for (int e = 0; e < 4; e++) acc[i][j][e] = 0.f;

    ldg(kbeg); sts(0); __syncthreads();
    const int KT = kslice >> 4;
    for (int kt = 0; kt < KT; kt++) {
        int buf = kt & 1;
        if (kt + 1 < KT) ldg(kbeg + (kt + 1) * 16);
        #pragma unroll
        for (int ks = 0; ks < 16; ks += 8) {
            uint32_t af[4][4], bf[4][2];
            #pragma unroll
            for (int i = 0; i < 4; i++) {
                const float* ap = &As[buf][(ks + fq) * SSTR + mb + 16*i + fr];
                af[i][0] = f2tf(ap[0]);
                af[i][1] = f2tf(ap[8]);
                af[i][2] = f2tf(ap[4*SSTR]);
                af[i][3] = f2tf(ap[4*SSTR + 8]);
            }
            #pragma unroll
            for (int j = 0; j < 4; j++) {
                const float* bp = &Bs[buf][(ks + fq) * SSTR + nb + 8*j + fr];
                bf[j][0] = f2tf(bp[0]);
                bf[j][1] = f2tf(bp[4*SSTR]);
            }
            #pragma unroll
            for (int i = 0; i < 4; i++)
                #pragma unroll
                for (int j = 0; j < 4; j++)
                    asm volatile(
                        "mma.sync.aligned.m16n8k8.row.col.f32.tf32.tf32.f32 "
                        "{%0,%1,%2,%3}, {%4,%5,%6,%7}, {%8,%9}, {%0,%1,%2,%3};"
                        : "+f"(acc[i][j][0]), "+f"(acc[i][j][1]),
                          "+f"(acc[i][j][2]), "+f"(acc[i][j][3])
                        : "r"(af[i][0]), "r"(af[i][1]), "r"(af[i][2]), "r"(af[i][3]),
                          "r"(bf[j][0]), "r"(bf[j][1]));
        }
        if (kt + 1 < KT) sts(buf ^ 1);
        __syncthreads();
    }

    if (nz > 1) {
        float* W = work + (size_t)z * M * N;
        #pragma unroll
        for (int i = 0; i < 4; i++) {
            int row = m0 + mb + 16*i + fr;
            #pragma unroll
            for (int j = 0; j < 4; j++) {
                int col = n0 + nb + 8*j + 2*fq;
                float2 v0 = {acc[i][j][0], acc[i][j][1]};
                float2 v1 = {acc[i][j][2], acc[i][j][3]};
                *(float2*)&W[(size_t)row * N + col]       = v0;
                *(float2*)&W[(size_t)(row + 8) * N + col] = v1;
            }
        }
    } else {
        #pragma unroll
        for (int i = 0; i < 4; i++) {
            int row = m0 + mb + 16*i + fr;
            #pragma unroll
            for (int j = 0; j < 4; j++) {
                int col = n0 + nb + 8*j + 2*fq;
                float v[4];
                #pragma unroll
                for (int e = 0; e < 4; e++) v[e] = alpha * acc[i][j][e];
                if (bias) {
                    float b0 = bias[col], b1 = bias[col + 1];
                    v[0] += b0; v[1] += b1; v[2] += b0; v[3] += b1;
                }
                float* c0 = C + (size_t)row * ldc + col;
                float* c1 = C + (size_t)(row + 8) * ldc + col;
                if (beta != 0.f) {
                    v[0] += beta * c0[0]; v[1] += beta * c0[1];
                    v[2] += beta * c1[0]; v[3] += beta * c1[1];
                }
                float2 v0 = {v[0], v[1]}, v1 = {v[2], v[3]};
                *(float2*)c0 = v0; *(float2*)c1 = v1;
            }
        }
    }
}

// ---------------- split-K reduce (float4-vectorized, fused epilogues) ----------------
// mode 0: C = beta*C + alpha*sum + bias?
// mode 1: z = alpha*sum + bias; C = z; gl = gelu(z)
// mode 2: C = alpha*sum * dgelu(zbuf)
__global__ void __launch_bounds__(256) reduce_k(
    const float* __restrict__ work, int nz, int MN, int N,
    float alpha, float beta, float* __restrict__ C,
    const float* __restrict__ bias,
    const float* __restrict__ zbuf, float* __restrict__ gl, int mode)
{
    int i4 = blockIdx.x * 256 + threadIdx.x;
    int MN4 = MN >> 2;
    const float4* w4 = (const float4*)work;
    float4 s = {0.f, 0.f, 0.f, 0.f};
    for (int zz = 0; zz < nz; zz++) {
        float4 p = w4[(size_t)zz * MN4 + i4];
        s.x += p.x; s.y += p.y; s.z += p.z; s.w += p.w;
    }
    s.x *= alpha; s.y *= alpha; s.z *= alpha; s.w *= alpha;
    int i = i4 << 2;
    int col = i % N;
    if (mode == 1) {
        float4 b4 = *(const float4*)&bias[col];
        s.x += b4.x; s.y += b4.y; s.z += b4.z; s.w += b4.w;
        *(float4*)&C[i] = s;
        float4 g = {gelu_f(s.x), gelu_f(s.y), gelu_f(s.z), gelu_f(s.w)};
        *(float4*)&gl[i] = g;
    } else if (mode == 2) {
        float4 z4 = *(const float4*)&zbuf[i];
        s.x *= dgelu_f(z4.x); s.y *= dgelu_f(z4.y);
        s.z *= dgelu_f(z4.z); s.w *= dgelu_f(z4.w);
        *(float4*)&C[i] = s;
    } else {
        if (bias) {
            float4 b4 = *(const float4*)&bias[col];
            s.x += b4.x; s.y += b4.y; s.z += b4.z; s.w += b4.w;
        }
        if (beta != 0.f) {
            float4 c4 = *(const float4*)&C[i];
            s.x += beta * c4.x; s.y += beta * c4.y;
            s.z += beta * c4.z; s.w += beta * c4.w;
        }
        *(float4*)&C[i] = s;
    }
}

// ---------------- reduce partials + residual + bias, then LayerNorm (float2) ----------------
__global__ void __launch_bounds__(256) reduce_ln(
    const float* __restrict__ work, int nz,
    const float* __restrict__ bias, const float* __restrict__ res,
    float* __restrict__ hout,
    const float* __restrict__ ls, const float* __restrict__ lb,
    float* __restrict__ y)
{
    __shared__ float red[256];
    int row = blockIdx.x, tid = threadIdx.x;
    size_t base = (size_t)row * D_;
    int c = tid * 2;
    float2 v = {0.f, 0.f};
    for (int z = 0; z < nz; z++) {
        float2 p = *(const float2*)&work[(size_t)z * MND_ + base + c];
        v.x += p.x; v.y += p.y;
    }
    float2 b2 = *(const float2*)&bias[c];
    float2 r2 = *(const float2*)&res[base + c];
    v.x += b2.x + r2.x; v.y += b2.y + r2.y;
    *(float2*)&hout[base + c] = v;

    red[tid] = v.x + v.y; __syncthreads();
    for (int w = 128; w > 0; w >>= 1) { if (tid < w) red[tid] += red[tid + w]; __syncthreads(); }
    float mean = red[0] * (1.f / D_); __syncthreads();
    float d0 = v.x - mean, d1 = v.y - mean;
    red[tid] = d0 * d0 + d1 * d1; __syncthreads();
    for (int w = 128; w > 0; w >>= 1) { if (tid < w) red[tid] += red[tid + w]; __syncthreads(); }
    float rstd = rsqrtf(red[0] * (1.f / D_) + 1e-5f);
    float2 s2 = *(const float2*)&ls[c];
    float2 o2 = *(const float2*)&lb[c];
    float2 out = {d0 * rstd * s2.x + o2.x, d1 * rstd * s2.y + o2.y};
    *(float2*)&y[base + c] = out;
}

// ---------------- fused embed + LN1(layer0) ----------------
__global__ void __launch_bounds__(256) embed_ln(const int* __restrict__ x,
    const float* __restrict__ emb, const float* __restrict__ pos, int off,
    float* __restrict__ h, const float* __restrict__ ls, const float* __restrict__ lb,
    float* __restrict__ y)
{
    __shared__ float red[256];
    int row = blockIdx.x, tid = threadIdx.x;
    int b = row >> 7, s = row & 127;
    int tok = x[b * T_ + off + s];
    size_t base = (size_t)row * D_;
    int c = tid * 2;
    float2 e2 = *(const float2*)&emb[(size_t)tok * D_ + c];
    float2 p2 = *(const float2*)&pos[s * D_ + c];
    float2 v = {e2.x + p2.x, e2.y + p2.y};
    *(float2*)&h[base + c] = v;

    red[tid] = v.x + v.y; __syncthreads();
    for (int w = 128; w > 0; w >>= 1) { if (tid < w) red[tid] += red[tid + w]; __syncthreads(); }
    float mean = red[0] * (1.f / D_); __syncthreads();
    float d0 = v.x - mean, d1 = v.y - mean;
    red[tid] = d0 * d0 + d1 * d1; __syncthreads();
    for (int w = 128; w > 0; w >>= 1) { if (tid < w) red[tid] += red[tid + w]; __syncthreads(); }
    float rstd = rsqrtf(red[0] * (1.f / D_) + 1e-5f);
    float2 s2 = *(const float2*)&ls[c];
    float2 o2 = *(const float2*)&lb[c];
    float2 out = {d0 * rstd * s2.x + o2.x, d1 * rstd * s2.y + o2.y};
    *(float2*)&y[base + c] = out;
}

// ---------------- LN backward with fused split-K partial sum (float2) ----------------
__global__ void __launch_bounds__(256) ln_bwd_f(const float* __restrict__ x,
    const float* __restrict__ work, int nz, const float* __restrict__ s,
    float* __restrict__ dacc, int accum)
{
    __shared__ float red[256];
    int row = blockIdx.x, tid = threadIdx.x;
    size_t base = (size_t)row * D_;
    int c = tid * 2;
    float2 dy = {0.f, 0.f};
    for (int z = 0; z < nz; z++) {
        float2 p = *(const float2*)&work[(size_t)z * MND_ + base + c];
        dy.x += p.x; dy.y += p.y;
    }
    float2 xv = *(const float2*)&x[base + c];
    red[tid] = xv.x + xv.y; __syncthreads();
    for (int w = 128; w > 0; w >>= 1) { if (tid < w) red[tid] += red[tid + w]; __syncthreads(); }
    float mean = red[0] * (1.f / D_); __syncthreads();
    float d0 = xv.x - mean, d1 = xv.y - mean;
    red[tid] = d0 * d0 + d1 * d1; __syncthreads();
    for (int w = 128; w > 0; w >>= 1) { if (tid < w) red[tid] += red[tid + w]; __syncthreads(); }
    float rstd = rsqrtf(red[0] * (1.f / D_) + 1e-5f); __syncthreads();
    float xh0 = d0 * rstd, xh1 = d1 * rstd;
    float2 s2 = *(const float2*)&s[c];
    float g0 = s2.x * dy.x, g1 = s2.y * dy.y;
    red[tid] = g0 + g1; __syncthreads();
    for (int w = 128; w > 0; w >>= 1) { if (tid < w) red[tid] += red[tid + w]; __syncthreads(); }
    float t1 = red[0] * (1.f / D_); __syncthreads();
    red[tid] = g0 * xh0 + g1 * xh1; __syncthreads();
    for (int w = 128; w > 0; w >>= 1) { if (tid < w) red[tid] += red[tid + w]; __syncthreads(); }
    float t2 = red[0] * (1.f / D_);
    float dx0 = rstd * (g0 - t1 - xh0 * t2);
    float dx1 = rstd * (g1 - t1 - xh1 * t2);
    float2* ar = (float2*)&dacc[base + c];
    if (accum) { float2 old = *ar; ar->x = old.x + dx0; ar->y = old.y + dx1; }
    else       { float2 nv = {dx0, dx1}; *ar = nv; }
}

// ---------------- attention forward ----------------
__global__ void __launch_bounds__(128) attn_fwd(const float* __restrict__ qkv,
    float* __restrict__ att, float* __restrict__ obuf)
{
    int qi = blockIdx.x, h = blockIdx.y, b = blockIdx.z, tid = threadIdx.x;
    __shared__ float qs[DH_]; __shared__ float sc[S_]; __shared__ float red[128];
    int row = b * S_ + qi;
    if (tid < DH_) qs[tid] = qkv[(size_t)row * (3*D_) + h * DH_ + tid];
    __syncthreads();
    float sj = -1e30f;
    if (tid <= qi) {
        const float* kp = qkv + (size_t)(b * S_ + tid) * (3*D_) + D_ + h * DH_;
        float a = 0.f;
        #pragma unroll
        for (int d = 0; d < DH_; d++) a += qs[d] * kp[d];
        sj = a * ASC_;
    }
    red[tid] = sj; __syncthreads();
    for (int w = 64; w > 0; w >>= 1) { if (tid < w) red[tid] = fmaxf(red[tid], red[tid + w]); __syncthreads(); }
    float mx = red[0]; __syncthreads();
    float e = (tid <= qi) ? expf(sj - mx) : 0.f;
    red[tid] = e; __syncthreads();
    for (int w = 64; w > 0; w >>= 1) { if (tid < w) red[tid] += red[tid + w]; __syncthreads(); }
    float a = e / red[0];
    size_t arow = ((size_t)(b * NH_ + h) * S_ + qi) * S_;
    att[arow + tid] = a;
    sc[tid] = a; __syncthreads();
    if (tid < DH_) {
        float acc = 0.f;
        for (int j = 0; j <= qi; j++)
            acc += sc[j] * qkv[(size_t)(b * S_ + j) * (3*D_) + 2*D_ + h * DH_ + tid];
        obuf[(size_t)row * D_ + h * DH_ + tid] = acc;
    }
}

// ---------------- attention backward 1 (fused dob partial-sum) ----------------
__global__ void __launch_bounds__(128) attn_bwd1(const float* __restrict__ qkv,
    const float* __restrict__ att, const float* __restrict__ work, int nz,
    float* __restrict__ dob, float* __restrict__ dsbuf, float* __restrict__ dqkv)
{
    int qi = blockIdx.x, h = blockIdx.y, b = blockIdx.z, tid = threadIdx.x;
    __shared__ float dov[DH_]; __shared__ float sc[S_]; __shared__ float red[128];
    int row = b * S_ + qi;
    if (tid < DH_) {
        size_t wi = (size_t)row * D_ + h * DH_ + tid;
        float s = 0.f;
        for (int z = 0; z < nz; z++) s += work[(size_t)z * MND_ + wi];
        dov[tid] = s;
        dob[wi] = s;
    }
    __syncthreads();
    size_t arow = ((size_t)(b * NH_ + h) * S_ + qi) * S_;
    float a = att[arow + tid];
    float datt = 0.f;
    if (tid <= qi) {
        const float* vp = qkv + (size_t)(b * S_ + tid) * (3*D_) + 2*D_ + h * DH_;
        #pragma unroll
        for (int d = 0; d < DH_; d++) datt += dov[d] * vp[d];
    }
    red[tid] = a * datt; __syncthreads();
    for (int w = 64; w > 0; w >>= 1) { if (tid < w) red[tid] += red[tid + w]; __syncthreads(); }
    float tot = red[0];
    float ds = a * (datt - tot);
    dsbuf[arow + tid] = ds;
    sc[tid] = ds; __syncthreads();
    if (tid < DH_) {
        float acc = 0.f;
        for (int j = 0; j <= qi; j++)
            acc += sc[j] * qkv[(size_t)(b * S_ + j) * (3*D_) + D_ + h * DH_ + tid];
        dqkv[(size_t)row * (3*D_) + h * DH_ + tid] = acc * ASC_;
    }
}

__global__ void __launch_bounds__(64) attn_bwd2(const float* __restrict__ qkv,
    const float* __restrict__ att, const float* __restrict__ dob,
    const float* __restrict__ dsbuf, float* __restrict__ dqkv)
{
    int j = blockIdx.x, h = blockIdx.y, b = blockIdx.z, d = threadIdx.x;
    size_t bh = (size_t)(b * NH_ + h) * S_;
    float dk = 0.f, dv = 0.f;
    for (int q = j; q < S_; q++) {
        float ds = dsbuf[(bh + q) * S_ + j];
        float a  = att[(bh + q) * S_ + j];
        dk += ds * qkv[(size_t)(b * S_ + q) * (3*D_) + h * DH_ + d];
        dv += a  * dob[(size_t)(b * S_ + q) * D_ + h * DH_ + d];
    }
    dqkv[(size_t)(b * S_ + j) * (3*D_) + D_   + h * DH_ + d] = dk * ASC_;
    dqkv[(size_t)(b * S_ + j) * (3*D_) + 2*D_ + h * DH_ + d] = dv;
}

// ---------------- both bias SGD updates in one launch ----------------
__global__ void __launch_bounds__(256) bias2_sgd(const float* __restrict__ dh,
    const float* __restrict__ dtH, float* __restrict__ b2, float* __restrict__ b1)
{
    int c = blockIdx.x * 256 + threadIdx.x;
    if (c < D_) {
        float s = 0.f;
        for (int i = 0; i < NT_; i++) s += dh[(size_t)i * D_ + c];
        b2[c] -= LR_ * s;
    } else {
        int c1 = c - D_;
        float s = 0.f;
        for (int i = 0; i < NT_; i++) s += dtH[(size_t)i * HID_ + c1];
        b1[c1] -= LR_ * s;
    }
}

// ---------------- fused softmax stats + dlogits ----------------
__global__ void __launch_bounds__(256) smax_dlog(const float* __restrict__ out,
    const int* __restrict__ x, int off, float* __restrict__ dl)
{
    __shared__ float red[256];
    int i = blockIdx.x, tid = threadIdx.x;
    int b = i >> 7, s = i & 127;
    const float* lp = out + ((size_t)(b * (NCH_*S_) + off + s)) * V_;
    float m = -1e30f;
    for (int v = tid; v < V_; v += 256) m = fmaxf(m, lp[v]);
    red[tid] = m; __syncthreads();
    for (int w = 128; w > 0; w >>= 1) { if (tid < w) red[tid] = fmaxf(red[tid], red[tid + w]); __syncthreads(); }
    m = red[0]; __syncthreads();
    float sum = 0.f;
    for (int v = tid; v < V_; v += 256) sum += expf(lp[v] - m);
    red[tid] = sum; __syncthreads();
    for (int w = 128; w > 0; w >>= 1) { if (tid < w) red[tid] += red[tid + w]; __syncthreads(); }
    float rinv = 1.f / red[0];
    int tgt = x[b * T_ + off + s + 1];
    float* dlr = dl + (size_t)i * V_;
    for (int v = tid; v < V_; v += 256) {
        float p = expf(lp[v] - m) * rinv;
        dlr[v] = (p - (v == tgt ? 1.f : 0.f)) * (1.f / NT_);
    }
}

// ---------------- segmented param copy (one launch) ----------------
#define NW1_ (L_*D_*HID_)
#define NW2_ (L_*HID_*D_)
#define NB1_ (L_*HID_)
#define NB2_ (L_*D_)
__global__ void __launch_bounds__(256) copy_params(
    const float* __restrict__ w1, const float* __restrict__ w2,
    const float* __restrict__ b1, const float* __restrict__ b2,
    float* __restrict__ pw1, float* __restrict__ pw2,
    float* __restrict__ pb1, float* __restrict__ pb2)
{
    int i = blockIdx.x * 256 + threadIdx.x;
    if (i < NW1_) { pw1[i] = w1[i]; }
    int j = i - NW1_;
    if (j >= 0 && j < NW2_) { pw2[j] = w2[j]; }
    int k = i - NW1_ - NW2_;
    if (k >= 0 && k < NB1_) { pb1[k] = b1[k]; }
    int l = i - NW1_ - NW2_ - NB1_;
    if (l >= 0 && l < NB2_) { pb2[l] = b2[l]; }
}

// ---------------- host ----------------
static float* P(const void* sym) { void* p = 0; cudaGetSymbolAddress(&p, sym); return (float*)p; }

static float* h_work;

static void gemmx(int TA, int TB, int M, int N, int K, int nz, float alpha,
                  const float* A, int lda, const float* B, int ldb,
                  float beta, float* C, int ldc, const float* bias)
{
    dim3 g(N / 128, M / 128, nz);
    if (!TA && !TB)      gemm128<0,0><<<g,256>>>(M,N,K,alpha,A,lda,B,ldb,beta,C,ldc,bias,h_work,0,0,0);
    else if (!TA && TB)  gemm128<0,1><<<g,256>>>(M,N,K,alpha,A,lda,B,ldb,beta,C,ldc,bias,h_work,0,0,0);
    else if (TA && !TB)  gemm128<1,0><<<g,256>>>(M,N,K,alpha,A,lda,B,ldb,beta,C,ldc,bias,h_work,0,0,0);
    else                 gemm128<1,1><<<g,256>>>(M,N,K,alpha,A,lda,B,ldb,beta,C,ldc,bias,h_work,0,0,0);
}

extern "C" void kernel_launch(void* const* d_in, const int* in_sizes, int n_in,
                              void* d_out, int out_size)
{
    const int*   x     = (const int*)  d_in[0];
    const float* emb   = (const float*)d_in[1];
    const float* pos   = (const float*)d_in[2];
    const float* ln1s  = (const float*)d_in[3];
    const float* ln1b  = (const float*)d_in[4];
    const float* Wqkv  = (const float*)d_in[5];
    const float* bqkv  = (const float*)d_in[6];
    const float* Wo    = (const float*)d_in[7];
    const float* bo    = (const float*)d_in[8];
    const float* ln2s  = (const float*)d_in[9];
    const float* ln2b  = (const float*)d_in[10];
    const float* W1i   = (const float*)d_in[11];
    const float* b1i   = (const float*)d_in[12];
    const float* W2i   = (const float*)d_in[13];
    const float* b2i   = (const float*)d_in[14];
    const float* lnfs  = (const float*)d_in[15];
    const float* lnfb  = (const float*)d_in[16];
    const float* Whead = (const float*)d_in[17];
    const float* bhead = (const float*)d_in[18];
    float* out = (float*)d_out;

    float *pW1 = P(g_W1), *pW2 = P(g_W2), *pb1 = P(g_b1), *pb2 = P(g_b2);
    float *ph = P(g_h), *phmid = P(g_hmid), *phfin = P(g_hfin), *pm = P(g_m);
    float *pqkv = P(g_qkv), *patt = P(g_att), *pz1 = P(g_z1), *pgl = P(g_gl);
    float *pabuf = P(g_abuf), *pobuf = P(g_obuf), *pdh = P(g_dh);
    float *pdtH = P(g_dtH), *pdob = P(g_dob);
    float *pdqkv = P(g_dqkv), *pds = P(g_ds), *pdlog = P(g_dlog);
    h_work = P(g_work);

    const int copyN = NW1_ + NW2_ + NB1_ + NB2_;
    copy_params<<<(copyN + 255)/256, 256>>>(W1i, W2i, b1i, b2i, pW1, pW2, pb1, pb2);

    for (int c = 0; c < NCH_; c++) {
        const int off = c * S_;

        // ---------------- forward ----------------
        embed_ln<<<NT_, 256>>>(x, emb, pos, off, ph, ln1s, ln1b, pabuf);
        for (int l = 0; l < L_; l++) {
            float* hin = ph + (size_t)l * ND_;
            float* hmid = phmid + (size_t)l * ND_;
            float* hout = (l < L_-1) ? ph + (size_t)(l+1)*ND_ : phfin;
            const float* nls = (l < L_-1) ? ln1s + (l+1)*D_ : lnfs;
            const float* nlb = (l < L_-1) ? ln1b + (l+1)*D_ : lnfb;

            gemmx(0,0, NT_, 3*D_, D_, 8, 1.f, pabuf, D_, Wqkv + (size_t)l*D_*3*D_, 3*D_, 0.f, 0, 0, 0);
            reduce_k<<<NQ_/1024, 256>>>(h_work, 8, NQ_, 3*D_, 1.f, 0.f,
                                        pqkv + (size_t)l*NQ_, bqkv + l*3*D_, 0, 0, 0);
            attn_fwd<<<dim3(S_,NH_,B_), 128>>>(pqkv + (size_t)l*NQ_, patt + (size_t)l*NA_, pobuf);
            gemmx(0,0, NT_, D_, D_, 16, 1.f, pobuf, D_, Wo + (size_t)l*D_*D_, D_, 0.f, 0, 0, 0);
            reduce_ln<<<NT_, 256>>>(h_work, 16, bo + l*D_, hin, hmid,
                                    ln2s + l*D_, ln2b + l*D_, pm + (size_t)l*ND_);
            gemmx(0,0, NT_, HID_, D_, 4, 1.f, pm + (size_t)l*ND_, D_, pW1 + (size_t)l*D_*HID_, HID_, 0.f, 0, 0, 0);
            reduce_k<<<NH1_/1024, 256>>>(h_work, 4, NH1_, HID_, 1.f, 0.f,
                                         pz1 + (size_t)l*NH1_, pb1 + l*HID_,
                                         0, pgl + (size_t)l*NH1_, 1);
            gemmx(0,0, NT_, D_, HID_, 16, 1.f, pgl + (size_t)l*NH1_, HID_, pW2 + (size_t)l*HID_*D_, D_, 0.f, 0, 0, 0);
            reduce_ln<<<NT_, 256>>>(h_work, 16, pb2 + l*D_, hmid, hout, nls, nlb, pabuf);
        }
        // logits: batched over B via blockIdx.z
        {
            dim3 g(V_ / 128, 1, B_);
            gemm128<0,0><<<g,256>>>(128, V_, D_, 1.f, pabuf, D_, Whead, V_,
                                    0.f, out + (size_t)off * V_, V_, bhead, h_work,
                                    1, (size_t)S_*D_, (size_t)(NCH_*S_)*V_);
        }

        // ---------------- backward ----------------
        smax_dlog<<<NT_, 256>>>(out, x, off, pdlog);
        gemmx(0,1, NT_, D_, V_, 20, 1.f, pdlog, V_, Whead, V_, 0.f, 0, 0, 0);
        ln_bwd_f<<<NT_, 256>>>(phfin, h_work, 20, lnfs, pdh, 0);

        for (int l = L_-1; l >= 0; l--) {
            gemmx(0,1, NT_, HID_, D_, 4, 1.f, pdh, D_, pW2 + (size_t)l*HID_*D_, D_, 0.f, 0, 0, 0);
            reduce_k<<<NH1_/1024, 256>>>(h_work, 4, NH1_, HID_, 1.f, 0.f, pdtH, 0,
                                         pz1 + (size_t)l*NH1_, 0, 2);
            gemmx(1,0, HID_, D_, NT_, 2, 1.f, pgl + (size_t)l*NH1_, HID_, pdh, D_, 0.f, 0, 0, 0);
            reduce_k<<<(HID_*D_)/1024, 256>>>(h_work, 2, HID_*D_, D_, -LR_, 1.f,
                                              pW2 + (size_t)l*HID_*D_, 0, 0, 0, 0);
            bias2_sgd<<<(D_+HID_)/256, 256>>>(pdh, pdtH, pb2 + l*D_, pb1 + l*HID_);
            gemmx(0,1, NT_, D_, HID_, 16, 1.f, pdtH, HID_, pW1 + (size_t)l*D_*HID_, HID_, 0.f, 0, 0, 0);
            ln_bwd_f<<<NT_, 256>>>(phmid + (size_t)l*ND_, h_work, 16, ln2s + l*D_, pdh, 1);
            gemmx(1,0, D_, HID_, NT_, 2, 1.f, pm + (size_t)l*ND_, D_, pdtH, HID_, 0.f, 0, 0, 0);
            reduce_k<<<(D_*HID_)/1024, 256>>>(h_work, 2, D_*HID_, HID_, -LR_, 1.f,
                                              pW1 + (size_t)l*D_*HID_, 0, 0, 0, 0);

            gemmx(0,1, NT_, D_, D_, 16, 1.f, pdh, D_, Wo + (size_t)l*D_*D_, D_, 0.f, 0, 0, 0);
            attn_bwd1<<<dim3(S_,NH_,B_), 128>>>(pqkv + (size_t)l*NQ_, patt + (size_t)l*NA_,
                                                h_work, 16, pdob, pds, pdqkv);
            attn_bwd2<<<dim3(S_,NH_,B_), 64>>>(pqkv + (size_t)l*NQ_, patt + (size_t)l*NA_,
                                               pdob, pds, pdqkv);
            gemmx(0,1, NT_, D_, 3*D_, 8, 1.f, pdqkv, 3*D_, Wqkv + (size_t)l*D_*3*D_, 3*D_, 0.f, 0, 0, 0);
            ln_bwd_f<<<NT_, 256>>>(ph + (size_t)l*ND_, h_work, 8, ln1s + l*D_, pdh, 1);
        }
    }
    (void)in_sizes; (void)n_in; (void)out_size;
}

// round 7
// speedup vs baseline: 3.9501x; 1.0066x over previous
#include <cuda_runtime.h>
#include <math.h>
#include <stdint.h>

#define D_    512
#define HID_  2048
#define L_    4
#define V_    32000
#define B_    2
#define T_    1025
#define S_    128
#define NH_   8
#define DH_   64
#define NT_   256
#define NCH_  8
#define LR_   0.0003f
#define ASC_  0.125f

#define ND_  (NT_*D_)
#define NH1_ (NT_*HID_)
#define NQ_  (NT_*3*D_)
#define NA_  (B_*NH_*S_*S_)
#define MND_ 131072           // 256*512

// ---------------- device scratch ----------------
__device__ float g_W1[L_*D_*HID_];
__device__ float g_W2[L_*HID_*D_];
__device__ float g_b1[L_*HID_];
__device__ float g_b2[L_*D_];
__device__ float g_h[L_*ND_];
__device__ float g_hmid[L_*ND_];
__device__ float g_hfin[ND_];
__device__ float g_m[L_*ND_];
__device__ float g_qkv[L_*NQ_];
__device__ float g_att[L_*NA_];
__device__ float g_z1[L_*NH1_];
__device__ float g_gl[L_*NH1_];
__device__ float g_abuf[ND_];
__device__ float g_obuf[ND_];
__device__ float g_dh[ND_];
__device__ float g_dtH[NH1_];
__device__ float g_dob[ND_];
__device__ float g_dqkv[NQ_];
__device__ float g_ds[NA_];
__device__ float g_dlog[NT_*V_];
__device__ float g_work[8*1024*1024];     // split-K partials (32 MB)

// ---------------- fast-math helpers ----------------
__device__ __forceinline__ float ftanh_(float u) {
    u = fminf(fmaxf(u, -15.f), 15.f);
    float e = __expf(2.f * u);
    return __fdividef(e - 1.f, e + 1.f);
}
__device__ __forceinline__ float gelu_f(float x) {
    float u = 0.7978845608028654f * (x + 0.044715f * x * x * x);
    return 0.5f * x * (1.f + ftanh_(u));
}
__device__ __forceinline__ float dgelu_f(float x) {
    float x2 = x * x;
    float u = 0.7978845608028654f * (x + 0.044715f * x * x2);
    float t = ftanh_(u);
    return 0.5f * (1.f + t)
         + 0.5f * x * (1.f - t * t) * 0.7978845608028654f * (1.f + 3.f * 0.044715f * x2);
}

__device__ __forceinline__ float f2tf_f(float f) {
    uint32_t u;
    asm("cvt.rna.tf32.f32 %0, %1;" : "=r"(u) : "f"(f));
    return __uint_as_float(u);
}

// ---------------- 128x128x16 tf32 tensor-core GEMM ----------------
// tf32 conversion is done ONCE at smem-store time; the mainloop loads raw bits.
// batched==0: gridDim.z = split-K count (nz>1 -> raw partials to work)
// batched==1: gridDim.z = batch index; full K; C/A offset by z strides
#define SSTR 132
template<int TA, int TB>
__global__ void __launch_bounds__(256) gemm128(
    int M, int N, int K, float alpha,
    const float* __restrict__ A, int lda,
    const float* __restrict__ B, int ldb,
    float beta, float* __restrict__ C, int ldc,
    const float* __restrict__ bias, float* __restrict__ work,
    int batched, size_t sAz, size_t sCz)
{
    __shared__ __align__(16) float As[2][16*SSTR];
    __shared__ __align__(16) float Bs[2][16*SSTR];
    const int tid = threadIdx.x;
    const int m0 = blockIdx.y * 128, n0 = blockIdx.x * 128;
    const int z = blockIdx.z;
    const int nz = batched ? 1 : gridDim.z;
    const int kslice = batched ? K : (K / gridDim.z);
    const int kbeg = batched ? 0 : z * kslice;
    if (batched) { A += (size_t)z * sAz; C += (size_t)z * sCz; }

    const int a_r = TA ? (tid >> 4) : (tid >> 1);
    const int a_c = TA ? ((tid & 15) * 8) : ((tid & 1) * 8);
    const int b_r = TB ? (tid >> 1) : (tid >> 4);
    const int b_c = TB ? ((tid & 1) * 8) : ((tid & 15) * 8);

    float4 pa0, pa1, pb0, pb1;

    auto ldg = [&](int kk) {
        const float* pa = TA ? (A + (size_t)(kk + a_r) * lda + m0 + a_c)
                             : (A + (size_t)(m0 + a_r) * lda + kk + a_c);
        pa0 = *(const float4*)pa; pa1 = *(const float4*)(pa + 4);
        const float* pb = TB ? (B + (size_t)(n0 + b_r) * ldb + kk + b_c)
                             : (B + (size_t)(kk + b_r) * ldb + n0 + b_c);
        pb0 = *(const float4*)pb; pb1 = *(const float4*)(pb + 4);
    };
    auto sts = [&](int buf) {
        float va[8] = {pa0.x,pa0.y,pa0.z,pa0.w,pa1.x,pa1.y,pa1.z,pa1.w};
        float vb[8] = {pb0.x,pb0.y,pb0.z,pb0.w,pb1.x,pb1.y,pb1.z,pb1.w};
        #pragma unroll
        for (int i = 0; i < 8; i++) va[i] = f2tf_f(va[i]);
        #pragma unroll
        for (int i = 0; i < 8; i++) vb[i] = f2tf_f(vb[i]);
        if (!TA) {
            #pragma unroll
            for (int i = 0; i < 8; i++) As[buf][(a_c + i) * SSTR + a_r] = va[i];
        } else {
            float4 w0 = {va[0],va[1],va[2],va[3]}, w1 = {va[4],va[5],va[6],va[7]};
            *(float4*)&As[buf][a_r * SSTR + a_c]     = w0;
            *(float4*)&As[buf][a_r * SSTR + a_c + 4] = w1;
        }
        if (!TB) {
            float4 w0 = {vb[0],vb[1],vb[2],vb[3]}, w1 = {vb[4],vb[5],vb[6],vb[7]};
            *(float4*)&Bs[buf][b_r * SSTR + b_c]     = w0;
            *(float4*)&Bs[buf][b_r * SSTR + b_c + 4] = w1;
        } else {
            #pragma unroll
            for (int i = 0; i < 8; i++) Bs[buf][(b_c + i) * SSTR + b_r] = vb[i];
        }
    };

    const int warp = tid >> 5, lane = tid & 31;
    const int mb = (warp >> 2) * 64;
    const int nb = (warp & 3) * 32;
    const int fr = lane >> 2, fq = lane & 3;

    float acc[4][4][4];
    #pragma unroll
    for (int i = 0; i < 4; i++)
        #pragma unroll
        for (int j = 0; j < 4; j++)
            #pragma unroll
            for (int e = 0; e < 4; e++) acc[i][j][e] = 0.f;

    ldg(kbeg); sts(0); __syncthreads();
    const int KT = kslice >> 4;
    for (int kt = 0; kt < KT; kt++) {
        int buf = kt & 1;
        if (kt + 1 < KT) ldg(kbeg + (kt + 1) * 16);
        #pragma unroll
        for (int ks = 0; ks < 16; ks += 8) {
            uint32_t af[4][4], bf[4][2];
            #pragma unroll
            for (int i = 0; i < 4; i++) {
                const float* ap = &As[buf][(ks + fq) * SSTR + mb + 16*i + fr];
                af[i][0] = __float_as_uint(ap[0]);
                af[i][1] = __float_as_uint(ap[8]);
                af[i][2] = __float_as_uint(ap[4*SSTR]);
                af[i][3] = __float_as_uint(ap[4*SSTR + 8]);
            }
            #pragma unroll
            for (int j = 0; j < 4; j++) {
                const float* bp = &Bs[buf][(ks + fq) * SSTR + nb + 8*j + fr];
                bf[j][0] = __float_as_uint(bp[0]);
                bf[j][1] = __float_as_uint(bp[4*SSTR]);
            }
            #pragma unroll
            for (int i = 0; i < 4; i++)
                #pragma unroll
                for (int j = 0; j < 4; j++)
                    asm volatile(
                        "mma.sync.aligned.m16n8k8.row.col.f32.tf32.tf32.f32 "
                        "{%0,%1,%2,%3}, {%4,%5,%6,%7}, {%8,%9}, {%0,%1,%2,%3};"
                        : "+f"(acc[i][j][0]), "+f"(acc[i][j][1]),
                          "+f"(acc[i][j][2]), "+f"(acc[i][j][3])
                        : "r"(af[i][0]), "r"(af[i][1]), "r"(af[i][2]), "r"(af[i][3]),
                          "r"(bf[j][0]), "r"(bf[j][1]));
        }
        if (kt + 1 < KT) sts(buf ^ 1);
        __syncthreads();
    }

    if (nz > 1) {
        float* W = work + (size_t)z * M * N;
        #pragma unroll
        for (int i = 0; i < 4; i++) {
            int row = m0 + mb + 16*i + fr;
            #pragma unroll
            for (int j = 0; j < 4; j++) {
                int col = n0 + nb + 8*j + 2*fq;
                float2 v0 = {acc[i][j][0], acc[i][j][1]};
                float2 v1 = {acc[i][j][2], acc[i][j][3]};
                *(float2*)&W[(size_t)row * N + col]       = v0;
                *(float2*)&W[(size_t)(row + 8) * N + col] = v1;
            }
        }
    } else {
        #pragma unroll
        for (int i = 0; i < 4; i++) {
            int row = m0 + mb + 16*i + fr;
            #pragma unroll
            for (int j = 0; j < 4; j++) {
                int col = n0 + nb + 8*j + 2*fq;
                float v[4];
                #pragma unroll
                for (int e = 0; e < 4; e++) v[e] = alpha * acc[i][j][e];
                if (bias) {
                    float b0 = bias[col], b1 = bias[col + 1];
                    v[0] += b0; v[1] += b1; v[2] += b0; v[3] += b1;
                }
                float* c0 = C + (size_t)row * ldc + col;
                float* c1 = C + (size_t)(row + 8) * ldc + col;
                if (beta != 0.f) {
                    v[0] += beta * c0[0]; v[1] += beta * c0[1];
                    v[2] += beta * c1[0]; v[3] += beta * c1[1];
                }
                float2 v0 = {v[0], v[1]}, v1 = {v[2], v[3]};
                *(float2*)c0 = v0; *(float2*)c1 = v1;
            }
        }
    }
}

// ---------------- split-K reduce (float4-vectorized, fused epilogues) ----------------
__global__ void __launch_bounds__(256) reduce_k(
    const float* __restrict__ work, int nz, int MN, int N,
    float alpha, float beta, float* __restrict__ C,
    const float* __restrict__ bias,
    const float* __restrict__ zbuf, float* __restrict__ gl, int mode)
{
    int i4 = blockIdx.x * 256 + threadIdx.x;
    int MN4 = MN >> 2;
    const float4* w4 = (const float4*)work;
    float4 s = {0.f, 0.f, 0.f, 0.f};
    for (int zz = 0; zz < nz; zz++) {
        float4 p = w4[(size_t)zz * MN4 + i4];
        s.x += p.x; s.y += p.y; s.z += p.z; s.w += p.w;
    }
    s.x *= alpha; s.y *= alpha; s.z *= alpha; s.w *= alpha;
    int i = i4 << 2;
    int col = i % N;
    if (mode == 1) {
        float4 b4 = *(const float4*)&bias[col];
        s.x += b4.x; s.y += b4.y; s.z += b4.z; s.w += b4.w;
        *(float4*)&C[i] = s;
        float4 g = {gelu_f(s.x), gelu_f(s.y), gelu_f(s.z), gelu_f(s.w)};
        *(float4*)&gl[i] = g;
    } else if (mode == 2) {
        float4 z4 = *(const float4*)&zbuf[i];
        s.x *= dgelu_f(z4.x); s.y *= dgelu_f(z4.y);
        s.z *= dgelu_f(z4.z); s.w *= dgelu_f(z4.w);
        *(float4*)&C[i] = s;
    } else {
        if (bias) {
            float4 b4 = *(const float4*)&bias[col];
            s.x += b4.x; s.y += b4.y; s.z += b4.z; s.w += b4.w;
        }
        if (beta != 0.f) {
            float4 c4 = *(const float4*)&C[i];
            s.x += beta * c4.x; s.y += beta * c4.y;
            s.z += beta * c4.z; s.w += beta * c4.w;
        }
        *(float4*)&C[i] = s;
    }
}

// ---------------- reduce partials + residual + bias, then LayerNorm (float2) ----------------
__global__ void __launch_bounds__(256) reduce_ln(
    const float* __restrict__ work, int nz,
    const float* __restrict__ bias, const float* __restrict__ res,
    float* __restrict__ hout,
    const float* __restrict__ ls, const float* __restrict__ lb,
    float* __restrict__ y)
{
    __shared__ float red[256];
    int row = blockIdx.x, tid = threadIdx.x;
    size_t base = (size_t)row * D_;
    int c = tid * 2;
    float2 v = {0.f, 0.f};
    for (int z = 0; z < nz; z++) {
        float2 p = *(const float2*)&work[(size_t)z * MND_ + base + c];
        v.x += p.x; v.y += p.y;
    }
    float2 b2 = *(const float2*)&bias[c];
    float2 r2 = *(const float2*)&res[base + c];
    v.x += b2.x + r2.x; v.y += b2.y + r2.y;
    *(float2*)&hout[base + c] = v;

    red[tid] = v.x + v.y; __syncthreads();
    for (int w = 128; w > 0; w >>= 1) { if (tid < w) red[tid] += red[tid + w]; __syncthreads(); }
    float mean = red[0] * (1.f / D_); __syncthreads();
    float d0 = v.x - mean, d1 = v.y - mean;
    red[tid] = d0 * d0 + d1 * d1; __syncthreads();
    for (int w = 128; w > 0; w >>= 1) { if (tid < w) red[tid] += red[tid + w]; __syncthreads(); }
    float rstd = rsqrtf(red[0] * (1.f / D_) + 1e-5f);
    float2 s2 = *(const float2*)&ls[c];
    float2 o2 = *(const float2*)&lb[c];
    float2 out = {d0 * rstd * s2.x + o2.x, d1 * rstd * s2.y + o2.y};
    *(float2*)&y[base + c] = out;
}

// ---------------- fused embed + LN1(layer0) ----------------
__global__ void __launch_bounds__(256) embed_ln(const int* __restrict__ x,
    const float* __restrict__ emb, const float* __restrict__ pos, int off,
    float* __restrict__ h, const float* __restrict__ ls, const float* __restrict__ lb,
    float* __restrict__ y)
{
    __shared__ float red[256];
    int row = blockIdx.x, tid = threadIdx.x;
    int b = row >> 7, s = row & 127;
    int tok = x[b * T_ + off + s];
    size_t base = (size_t)row * D_;
    int c = tid * 2;
    float2 e2 = *(const float2*)&emb[(size_t)tok * D_ + c];
    float2 p2 = *(const float2*)&pos[s * D_ + c];
    float2 v = {e2.x + p2.x, e2.y + p2.y};
    *(float2*)&h[base + c] = v;

    red[tid] = v.x + v.y; __syncthreads();
    for (int w = 128; w > 0; w >>= 1) { if (tid < w) red[tid] += red[tid + w]; __syncthreads(); }
    float mean = red[0] * (1.f / D_); __syncthreads();
    float d0 = v.x - mean, d1 = v.y - mean;
    red[tid] = d0 * d0 + d1 * d1; __syncthreads();
    for (int w = 128; w > 0; w >>= 1) { if (tid < w) red[tid] += red[tid + w]; __syncthreads(); }
    float rstd = rsqrtf(red[0] * (1.f / D_) + 1e-5f);
    float2 s2 = *(const float2*)&ls[c];
    float2 o2 = *(const float2*)&lb[c];
    float2 out = {d0 * rstd * s2.x + o2.x, d1 * rstd * s2.y + o2.y};
    *(float2*)&y[base + c] = out;
}

// ---------------- LN backward with fused split-K partial sum (float2) ----------------
__global__ void __launch_bounds__(256) ln_bwd_f(const float* __restrict__ x,
    const float* __restrict__ work, int nz, const float* __restrict__ s,
    float* __restrict__ dacc, int accum)
{
    __shared__ float red[256];
    int row = blockIdx.x, tid = threadIdx.x;
    size_t base = (size_t)row * D_;
    int c = tid * 2;
    float2 dy = {0.f, 0.f};
    for (int z = 0; z < nz; z++) {
        float2 p = *(const float2*)&work[(size_t)z * MND_ + base + c];
        dy.x += p.x; dy.y += p.y;
    }
    float2 xv = *(const float2*)&x[base + c];
    red[tid] = xv.x + xv.y; __syncthreads();
    for (int w = 128; w > 0; w >>= 1) { if (tid < w) red[tid] += red[tid + w]; __syncthreads(); }
    float mean = red[0] * (1.f / D_); __syncthreads();
    float d0 = xv.x - mean, d1 = xv.y - mean;
    red[tid] = d0 * d0 + d1 * d1; __syncthreads();
    for (int w = 128; w > 0; w >>= 1) { if (tid < w) red[tid] += red[tid + w]; __syncthreads(); }
    float rstd = rsqrtf(red[0] * (1.f / D_) + 1e-5f); __syncthreads();
    float xh0 = d0 * rstd, xh1 = d1 * rstd;
    float2 s2 = *(const float2*)&s[c];
    float g0 = s2.x * dy.x, g1 = s2.y * dy.y;
    red[tid] = g0 + g1; __syncthreads();
    for (int w = 128; w > 0; w >>= 1) { if (tid < w) red[tid] += red[tid + w]; __syncthreads(); }
    float t1 = red[0] * (1.f / D_); __syncthreads();
    red[tid] = g0 * xh0 + g1 * xh1; __syncthreads();
    for (int w = 128; w > 0; w >>= 1) { if (tid < w) red[tid] += red[tid + w]; __syncthreads(); }
    float t2 = red[0] * (1.f / D_);
    float dx0 = rstd * (g0 - t1 - xh0 * t2);
    float dx1 = rstd * (g1 - t1 - xh1 * t2);
    float2* ar = (float2*)&dacc[base + c];
    if (accum) { float2 old = *ar; ar->x = old.x + dx0; ar->y = old.y + dx1; }
    else       { float2 nv = {dx0, dx1}; *ar = nv; }
}

// ---------------- attention forward ----------------
__global__ void __launch_bounds__(128) attn_fwd(const float* __restrict__ qkv,
    float* __restrict__ att, float* __restrict__ obuf)
{
    int qi = blockIdx.x, h = blockIdx.y, b = blockIdx.z, tid = threadIdx.x;
    __shared__ float qs[DH_]; __shared__ float sc[S_]; __shared__ float red[128];
    int row = b * S_ + qi;
    if (tid < DH_) qs[tid] = qkv[(size_t)row * (3*D_) + h * DH_ + tid];
    __syncthreads();
    float sj = -1e30f;
    if (tid <= qi) {
        const float* kp = qkv + (size_t)(b * S_ + tid) * (3*D_) + D_ + h * DH_;
        float a = 0.f;
        #pragma unroll
        for (int d = 0; d < DH_; d++) a += qs[d] * kp[d];
        sj = a * ASC_;
    }
    red[tid] = sj; __syncthreads();
    for (int w = 64; w > 0; w >>= 1) { if (tid < w) red[tid] = fmaxf(red[tid], red[tid + w]); __syncthreads(); }
    float mx = red[0]; __syncthreads();
    float e = (tid <= qi) ? __expf(sj - mx) : 0.f;
    red[tid] = e; __syncthreads();
    for (int w = 64; w > 0; w >>= 1) { if (tid < w) red[tid] += red[tid + w]; __syncthreads(); }
    float a = e / red[0];
    size_t arow = ((size_t)(b * NH_ + h) * S_ + qi) * S_;
    att[arow + tid] = a;
    sc[tid] = a; __syncthreads();
    if (tid < DH_) {
        float acc = 0.f;
        for (int j = 0; j <= qi; j++)
            acc += sc[j] * qkv[(size_t)(b * S_ + j) * (3*D_) + 2*D_ + h * DH_ + tid];
        obuf[(size_t)row * D_ + h * DH_ + tid] = acc;
    }
}

// ---------------- attention backward 1 (fused dob partial-sum) ----------------
__global__ void __launch_bounds__(128) attn_bwd1(const float* __restrict__ qkv,
    const float* __restrict__ att, const float* __restrict__ work, int nz,
    float* __restrict__ dob, float* __restrict__ dsbuf, float* __restrict__ dqkv)
{
    int qi = blockIdx.x, h = blockIdx.y, b = blockIdx.z, tid = threadIdx.x;
    __shared__ float dov[DH_]; __shared__ float sc[S_]; __shared__ float red[128];
    int row = b * S_ + qi;
    if (tid < DH_) {
        size_t wi = (size_t)row * D_ + h * DH_ + tid;
        float s = 0.f;
        for (int z = 0; z < nz; z++) s += work[(size_t)z * MND_ + wi];
        dov[tid] = s;
        dob[wi] = s;
    }
    __syncthreads();
    size_t arow = ((size_t)(b * NH_ + h) * S_ + qi) * S_;
    float a = att[arow + tid];
    float datt = 0.f;
    if (tid <= qi) {
        const float* vp = qkv + (size_t)(b * S_ + tid) * (3*D_) + 2*D_ + h * DH_;
        #pragma unroll
        for (int d = 0; d < DH_; d++) datt += dov[d] * vp[d];
    }
    red[tid] = a * datt; __syncthreads();
    for (int w = 64; w > 0; w >>= 1) { if (tid < w) red[tid] += red[tid + w]; __syncthreads(); }
    float tot = red[0];
    float ds = a * (datt - tot);
    dsbuf[arow + tid] = ds;
    sc[tid] = ds; __syncthreads();
    if (tid < DH_) {
        float acc = 0.f;
        for (int j = 0; j <= qi; j++)
            acc += sc[j] * qkv[(size_t)(b * S_ + j) * (3*D_) + D_ + h * DH_ + tid];
        dqkv[(size_t)row * (3*D_) + h * DH_ + tid] = acc * ASC_;
    }
}

__global__ void __launch_bounds__(64) attn_bwd2(const float* __restrict__ qkv,
    const float* __restrict__ att, const float* __restrict__ dob,
    const float* __restrict__ dsbuf, float* __restrict__ dqkv)
{
    int j = blockIdx.x, h = blockIdx.y, b = blockIdx.z, d = threadIdx.x;
    size_t bh = (size_t)(b * NH_ + h) * S_;
    float dk = 0.f, dv = 0.f;
    for (int q = j; q < S_; q++) {
        float ds = dsbuf[(bh + q) * S_ + j];
        float a  = att[(bh + q) * S_ + j];
        dk += ds * qkv[(size_t)(b * S_ + q) * (3*D_) + h * DH_ + d];
        dv += a  * dob[(size_t)(b * S_ + q) * D_ + h * DH_ + d];
    }
    dqkv[(size_t)(b * S_ + j) * (3*D_) + D_   + h * DH_ + d] = dk * ASC_;
    dqkv[(size_t)(b * S_ + j) * (3*D_) + 2*D_ + h * DH_ + d] = dv;
}

// ---------------- both bias SGD updates in one launch ----------------
__global__ void __launch_bounds__(256) bias2_sgd(const float* __restrict__ dh,
    const float* __restrict__ dtH, float* __restrict__ b2, float* __restrict__ b1)
{
    int c = blockIdx.x * 256 + threadIdx.x;
    if (c < D_) {
        float s = 0.f;
        for (int i = 0; i < NT_; i++) s += dh[(size_t)i * D_ + c];
        b2[c] -= LR_ * s;
    } else {
        int c1 = c - D_;
        float s = 0.f;
        for (int i = 0; i < NT_; i++) s += dtH[(size_t)i * HID_ + c1];
        b1[c1] -= LR_ * s;
    }
}

// ---------------- fused online softmax stats + dlogits (512 thr, float4) ----------------
__global__ void __launch_bounds__(512) smax_dlog(const float* __restrict__ out,
    const int* __restrict__ x, int off, float* __restrict__ dl)
{
    __shared__ float rm[512], rs[512];
    int i = blockIdx.x, tid = threadIdx.x;
    int b = i >> 7, s = i & 127;
    const float* lp = out + ((size_t)(b * (NCH_*S_) + off + s)) * V_;
    const float4* lp4 = (const float4*)lp;

    // online max+sum in one pass
    float m = -1e30f, sum = 0.f;
    for (int v4 = tid; v4 < V_/4; v4 += 512) {
        float4 q = lp4[v4];
        float vals[4] = {q.x, q.y, q.z, q.w};
        #pragma unroll
        for (int e = 0; e < 4; e++) {
            float v = vals[e];
            if (v > m) { sum *= __expf(m - v); m = v; }
            sum += __expf(v - m);
        }
    }
    rm[tid] = m; rs[tid] = sum; __syncthreads();
    for (int w = 256; w > 0; w >>= 1) {
        if (tid < w) {
            float m1 = rm[tid], m2 = rm[tid + w];
            float M = fmaxf(m1, m2);
            rs[tid] = rs[tid] * __expf(m1 - M) + rs[tid + w] * __expf(m2 - M);
            rm[tid] = M;
        }
        __syncthreads();
    }
    m = rm[0];
    float rinv = __fdividef(1.f, rs[0]);
    const float invNT = 1.f / NT_;
    int tgt = x[b * T_ + off + s + 1];

    float4* dl4 = (float4*)(dl + (size_t)i * V_);
    for (int v4 = tid; v4 < V_/4; v4 += 512) {
        float4 q = lp4[v4];
        int vb = v4 * 4;
        float4 p;
        p.x = (__expf(q.x - m) * rinv - (vb + 0 == tgt ? 1.f : 0.f)) * invNT;
        p.y = (__expf(q.y - m) * rinv - (vb + 1 == tgt ? 1.f : 0.f)) * invNT;
        p.z = (__expf(q.z - m) * rinv - (vb + 2 == tgt ? 1.f : 0.f)) * invNT;
        p.w = (__expf(q.w - m) * rinv - (vb + 3 == tgt ? 1.f : 0.f)) * invNT;
        dl4[v4] = p;
    }
}

// ---------------- segmented param copy (one launch) ----------------
#define NW1_ (L_*D_*HID_)
#define NW2_ (L_*HID_*D_)
#define NB1_ (L_*HID_)
#define NB2_ (L_*D_)
__global__ void __launch_bounds__(256) copy_params(
    const float* __restrict__ w1, const float* __restrict__ w2,
    const float* __restrict__ b1, const float* __restrict__ b2,
    float* __restrict__ pw1, float* __restrict__ pw2,
    float* __restrict__ pb1, float* __restrict__ pb2)
{
    int i = blockIdx.x * 256 + threadIdx.x;
    if (i < NW1_) { pw1[i] = w1[i]; }
    int j = i - NW1_;
    if (j >= 0 && j < NW2_) { pw2[j] = w2[j]; }
    int k = i - NW1_ - NW2_;
    if (k >= 0 && k < NB1_) { pb1[k] = b1[k]; }
    int l = i - NW1_ - NW2_ - NB1_;
    if (l >= 0 && l < NB2_) { pb2[l] = b2[l]; }
}

// ---------------- host ----------------
static float* P(const void* sym) { void* p = 0; cudaGetSymbolAddress(&p, sym); return (float*)p; }

static float* h_work;

static void gemmx(int TA, int TB, int M, int N, int K, int nz, float alpha,
                  const float* A, int lda, const float* B, int ldb,
                  float beta, float* C, int ldc, const float* bias)
{
    dim3 g(N / 128, M / 128, nz);
    if (!TA && !TB)      gemm128<0,0><<<g,256>>>(M,N,K,alpha,A,lda,B,ldb,beta,C,ldc,bias,h_work,0,0,0);
    else if (!TA && TB)  gemm128<0,1><<<g,256>>>(M,N,K,alpha,A,lda,B,ldb,beta,C,ldc,bias,h_work,0,0,0);
    else if (TA && !TB)  gemm128<1,0><<<g,256>>>(M,N,K,alpha,A,lda,B,ldb,beta,C,ldc,bias,h_work,0,0,0);
    else                 gemm128<1,1><<<g,256>>>(M,N,K,alpha,A,lda,B,ldb,beta,C,ldc,bias,h_work,0,0,0);
}

extern "C" void kernel_launch(void* const* d_in, const int* in_sizes, int n_in,
                              void* d_out, int out_size)
{
    const int*   x     = (const int*)  d_in[0];
    const float* emb   = (const float*)d_in[1];
    const float* pos   = (const float*)d_in[2];
    const float* ln1s  = (const float*)d_in[3];
    const float* ln1b  = (const float*)d_in[4];
    const float* Wqkv  = (const float*)d_in[5];
    const float* bqkv  = (const float*)d_in[6];
    const float* Wo    = (const float*)d_in[7];
    const float* bo    = (const float*)d_in[8];
    const float* ln2s  = (const float*)d_in[9];
    const float* ln2b  = (const float*)d_in[10];
    const float* W1i   = (const float*)d_in[11];
    const float* b1i   = (const float*)d_in[12];
    const float* W2i   = (const float*)d_in[13];
    const float* b2i   = (const float*)d_in[14];
    const float* lnfs  = (const float*)d_in[15];
    const float* lnfb  = (const float*)d_in[16];
    const float* Whead = (const float*)d_in[17];
    const float* bhead = (const float*)d_in[18];
    float* out = (float*)d_out;

    float *pW1 = P(g_W1), *pW2 = P(g_W2), *pb1 = P(g_b1), *pb2 = P(g_b2);
    float *ph = P(g_h), *phmid = P(g_hmid), *phfin = P(g_hfin), *pm = P(g_m);
    float *pqkv = P(g_qkv), *patt = P(g_att), *pz1 = P(g_z1), *pgl = P(g_gl);
    float *pabuf = P(g_abuf), *pobuf = P(g_obuf), *pdh = P(g_dh);
    float *pdtH = P(g_dtH), *pdob = P(g_dob);
    float *pdqkv = P(g_dqkv), *pds = P(g_ds), *pdlog = P(g_dlog);
    h_work = P(g_work);

    const int copyN = NW1_ + NW2_ + NB1_ + NB2_;
    copy_params<<<(copyN + 255)/256, 256>>>(W1i, W2i, b1i, b2i, pW1, pW2, pb1, pb2);

    for (int c = 0; c < NCH_; c++) {
        const int off = c * S_;

        // ---------------- forward ----------------
        embed_ln<<<NT_, 256>>>(x, emb, pos, off, ph, ln1s, ln1b, pabuf);
        for (int l = 0; l < L_; l++) {
            float* hin = ph + (size_t)l * ND_;
            float* hmid = phmid + (size_t)l * ND_;
            float* hout = (l < L_-1) ? ph + (size_t)(l+1)*ND_ : phfin;
            const float* nls = (l < L_-1) ? ln1s + (l+1)*D_ : lnfs;
            const float* nlb = (l < L_-1) ? ln1b + (l+1)*D_ : lnfb;

            gemmx(0,0, NT_, 3*D_, D_, 8, 1.f, pabuf, D_, Wqkv + (size_t)l*D_*3*D_, 3*D_, 0.f, 0, 0, 0);
            reduce_k<<<NQ_/1024, 256>>>(h_work, 8, NQ_, 3*D_, 1.f, 0.f,
                                        pqkv + (size_t)l*NQ_, bqkv + l*3*D_, 0, 0, 0);
            attn_fwd<<<dim3(S_,NH_,B_), 128>>>(pqkv + (size_t)l*NQ_, patt + (size_t)l*NA_, pobuf);
            gemmx(0,0, NT_, D_, D_, 16, 1.f, pobuf, D_, Wo + (size_t)l*D_*D_, D_, 0.f, 0, 0, 0);
            reduce_ln<<<NT_, 256>>>(h_work, 16, bo + l*D_, hin, hmid,
                                    ln2s + l*D_, ln2b + l*D_, pm + (size_t)l*ND_);
            gemmx(0,0, NT_, HID_, D_, 4, 1.f, pm + (size_t)l*ND_, D_, pW1 + (size_t)l*D_*HID_, HID_, 0.f, 0, 0, 0);
            reduce_k<<<NH1_/1024, 256>>>(h_work, 4, NH1_, HID_, 1.f, 0.f,
                                         pz1 + (size_t)l*NH1_, pb1 + l*HID_,
                                         0, pgl + (size_t)l*NH1_, 1);
            gemmx(0,0, NT_, D_, HID_, 16, 1.f, pgl + (size_t)l*NH1_, HID_, pW2 + (size_t)l*HID_*D_, D_, 0.f, 0, 0, 0);
            reduce_ln<<<NT_, 256>>>(h_work, 16, pb2 + l*D_, hmid, hout, nls, nlb, pabuf);
        }
        // logits: batched over B via blockIdx.z
        {
            dim3 g(V_ / 128, 1, B_);
            gemm128<0,0><<<g,256>>>(128, V_, D_, 1.f, pabuf, D_, Whead, V_,
                                    0.f, out + (size_t)off * V_, V_, bhead, h_work,
                                    1, (size_t)S_*D_, (size_t)(NCH_*S_)*V_);
        }

        // ---------------- backward ----------------
        smax_dlog<<<NT_, 512>>>(out, x, off, pdlog);
        gemmx(0,1, NT_, D_, V_, 20, 1.f, pdlog, V_, Whead, V_, 0.f, 0, 0, 0);
        ln_bwd_f<<<NT_, 256>>>(phfin, h_work, 20, lnfs, pdh, 0);

        for (int l = L_-1; l >= 0; l--) {
            gemmx(0,1, NT_, HID_, D_, 4, 1.f, pdh, D_, pW2 + (size_t)l*HID_*D_, D_, 0.f, 0, 0, 0);
            reduce_k<<<NH1_/1024, 256>>>(h_work, 4, NH1_, HID_, 1.f, 0.f, pdtH, 0,
                                         pz1 + (size_t)l*NH1_, 0, 2);
            gemmx(1,0, HID_, D_, NT_, 2, 1.f, pgl + (size_t)l*NH1_, HID_, pdh, D_, 0.f, 0, 0, 0);
            reduce_k<<<(HID_*D_)/1024, 256>>>(h_work, 2, HID_*D_, D_, -LR_, 1.f,
                                              pW2 + (size_t)l*HID_*D_, 0, 0, 0, 0);
            bias2_sgd<<<(D_+HID_)/256, 256>>>(pdh, pdtH, pb2 + l*D_, pb1 + l*HID_);
            gemmx(0,1, NT_, D_, HID_, 16, 1.f, pdtH, HID_, pW1 + (size_t)l*D_*HID_, HID_, 0.f, 0, 0, 0);
            ln_bwd_f<<<NT_, 256>>>(phmid + (size_t)l*ND_, h_work, 16, ln2s + l*D_, pdh, 1);
            gemmx(1,0, D_, HID_, NT_, 2, 1.f, pm + (size_t)l*ND_, D_, pdtH, HID_, 0.f, 0, 0, 0);
            reduce_k<<<(D_*HID_)/1024, 256>>>(h_work, 2, D_*HID_, HID_, -LR_, 1.f,
                                              pW1 + (size_t)l*D_*HID_, 0, 0, 0, 0);

            gemmx(0,1, NT_, D_, D_, 16, 1.f, pdh, D_, Wo + (size_t)l*D_*D_, D_, 0.f, 0, 0, 0);
            attn_bwd1<<<dim3(S_,NH_,B_), 128>>>(pqkv + (size_t)l*NQ_, patt + (size_t)l*NA_,
                                                h_work, 16, pdob, pds, pdqkv);
            attn_bwd2<<<dim3(S_,NH_,B_), 64>>>(pqkv + (size_t)l*NQ_, patt + (size_t)l*NA_,
                                               pdob, pds, pdqkv);
            gemmx(0,1, NT_, D_, 3*D_, 8, 1.f, pdqkv, 3*D_, Wqkv + (size_t)l*D_*3*D_, 3*D_, 0.f, 0, 0, 0);
            ln_bwd_f<<<NT_, 256>>>(ph + (size_t)l*ND_, h_work, 8, ln1s + l*D_, pdh, 1);
        }
    }
    (void)in_sizes; (void)n_in; (void)out_size;
}